// round 4
// baseline (speedup 1.0000x reference)
#include <cuda_runtime.h>

#define HIDDEN   2048
#define KVSIZE   512
#define HEADS    32
#define HEAD_DIM 64
#define BATCH    2
#define SEQ      2048
#define MTOT     (BATCH * SEQ)

#define BM 64
#define BN 64
#define KT_STRIDE 68   // padded stride for transposed K / P tile (bank-conflict relief)

// Scratch (device globals: allocation inside kernel_launch is forbidden)
__device__ float g_Q[MTOT * HIDDEN];   // [m][h*64+d]
__device__ float g_K[MTOT * KVSIZE];   // [m][kvh*64+d]
__device__ float g_V[MTOT * KVSIZE];
__device__ float g_A[MTOT * HIDDEN];   // attention output, same layout as g_Q

// ---------------------------------------------------------------------------
// C[M,N] = A[M,K] @ B[K,N] + bias[N]   (all fp32, M%128==0, N%128==0, K%16==0)
// 128x128 block tile, BK=16, 256 threads, 8x8 per-thread micro-tile.
// ---------------------------------------------------------------------------
__global__ __launch_bounds__(256) void gemm_bias(
    const float* __restrict__ A, const float* __restrict__ B,
    const float* __restrict__ bias, float* __restrict__ C,
    int M, int N, int K)
{
    __shared__ float As[16][128];   // transposed A tile: As[k][m]
    __shared__ float Bs[16][128];   // Bs[k][n]

    const int tid = threadIdx.x;
    const int tx = tid & 15;        // 0..15 -> 8 output cols
    const int ty = tid >> 4;        // 0..15 -> 8 output rows
    const int brow = blockIdx.y * 128;
    const int bcol = blockIdx.x * 128;

    float acc[8][8];
#pragma unroll
    for (int i = 0; i < 8; i++)
#pragma unroll
        for (int j = 0; j < 8; j++) acc[i][j] = 0.0f;

    for (int kt = 0; kt < K; kt += 16) {
        // Load A tile (128x16), store transposed
#pragma unroll
        for (int it = 0; it < 2; it++) {
            int f = tid + it * 256;           // 0..511 float4 slots
            int r  = f >> 2;                  // 0..127
            int c4 = (f & 3) << 2;            // 0,4,8,12
            float4 v = *(const float4*)&A[(brow + r) * K + kt + c4];
            As[c4 + 0][r] = v.x;
            As[c4 + 1][r] = v.y;
            As[c4 + 2][r] = v.z;
            As[c4 + 3][r] = v.w;
        }
        // Load B tile (16x128), natural layout
#pragma unroll
        for (int it = 0; it < 2; it++) {
            int f = tid + it * 256;
            int r  = f >> 5;                  // 0..15
            int c4 = (f & 31) << 2;           // 0..124
            *(float4*)&Bs[r][c4] = *(const float4*)&B[(kt + r) * N + bcol + c4];
        }
        __syncthreads();

#pragma unroll
        for (int k = 0; k < 16; k++) {
            float a[8], b[8];
            *(float4*)&a[0] = *(float4*)&As[k][ty * 8];
            *(float4*)&a[4] = *(float4*)&As[k][ty * 8 + 4];
            *(float4*)&b[0] = *(float4*)&Bs[k][tx * 8];
            *(float4*)&b[4] = *(float4*)&Bs[k][tx * 8 + 4];
#pragma unroll
            for (int i = 0; i < 8; i++)
#pragma unroll
                for (int j = 0; j < 8; j++)
                    acc[i][j] += a[i] * b[j];
        }
        __syncthreads();
    }

    // Epilogue: bias + store
#pragma unroll
    for (int i = 0; i < 8; i++) {
        int row = brow + ty * 8 + i;
        float* Crow = &C[row * N + bcol + tx * 8];
#pragma unroll
        for (int j = 0; j < 8; j += 4) {
            float4 o;
            o.x = acc[i][j + 0] + bias[bcol + tx * 8 + j + 0];
            o.y = acc[i][j + 1] + bias[bcol + tx * 8 + j + 1];
            o.z = acc[i][j + 2] + bias[bcol + tx * 8 + j + 2];
            o.w = acc[i][j + 3] + bias[bcol + tx * 8 + j + 3];
            *(float4*)&Crow[j] = o;
        }
    }
}

// ---------------------------------------------------------------------------
// Fused attention with online softmax.
// Grid: (SEQ/BM, HEADS, BATCH). Block: 256 threads = 16x16.
// Thread (ty,tx) owns 4 query rows (ty*4+i) x 4 cols (tx*4+j); the "col" axis
// is keys during QK^T and head-dims during PV.
// Shared layout (dynamic, 50176 B):
//   Qt [64][64]      k-major (Qt[d][row]), stride 64
//   Kt [64][68]      k-major (Kt[d][key]), stride 68; reused as Pt[key][row]
//   Vs [64][64]      natural (Vs[key][d]), stride 64
// ---------------------------------------------------------------------------
extern __shared__ float fa_smem[];

__global__ __launch_bounds__(256) void flash_attn(const float* __restrict__ mask)
{
    float* Qt = fa_smem;                       // 4096 floats
    float* Kt = fa_smem + 64 * 64;             // 4352 floats (also Pt)
    float* Vs = Kt + 64 * KT_STRIDE;           // 4096 floats

    const int tid = threadIdx.x;
    const int tx = tid & 15;
    const int ty = tid >> 4;
    const int h   = blockIdx.y;                // 0..31
    const int b   = blockIdx.z;
    const int kvh = h >> 2;
    const int m0  = b * SEQ + blockIdx.x * BM; // global row of first query
    const float* maskb = mask + b * SEQ;
    const float scale = 0.125f;                // 1/sqrt(64)

    // Load Q tile -> Qt[d][row] (coalesced global read; one-time scatter store)
#pragma unroll
    for (int t = 0; t < 16; t++) {
        int lin = t * 256 + tid;               // 0..4095
        int row = lin >> 6;
        int d   = lin & 63;
        Qt[d * 64 + row] = g_Q[(m0 + row) * HIDDEN + h * HEAD_DIM + d];
    }

    float m_i[4], l_i[4], o[4][4];
#pragma unroll
    for (int i = 0; i < 4; i++) {
        m_i[i] = -1e30f;
        l_i[i] = 0.0f;
#pragma unroll
        for (int j = 0; j < 4; j++) o[i][j] = 0.0f;
    }

    for (int kt = 0; kt < SEQ; kt += BN) {
        __syncthreads();   // previous tile's PV reads done; Q visible on 1st iter

        // Load K (transposed, padded) and V (natural)
#pragma unroll
        for (int t = 0; t < 16; t++) {
            int lin = t * 256 + tid;
            int key = lin >> 6;
            int d   = lin & 63;
            int gidx = (b * SEQ + kt + key) * KVSIZE + kvh * HEAD_DIM + d;
            Kt[d * KT_STRIDE + key] = g_K[gidx];
            Vs[key * 64 + d]        = g_V[gidx];
        }
        __syncthreads();

        // S = Q K^T
        float s[4][4];
#pragma unroll
        for (int i = 0; i < 4; i++)
#pragma unroll
            for (int j = 0; j < 4; j++) s[i][j] = 0.0f;

#pragma unroll 8
        for (int d = 0; d < 64; d++) {
            float4 qv = *(float4*)(Qt + d * 64 + ty * 4);
            float4 kv = *(float4*)(Kt + d * KT_STRIDE + tx * 4);
            float qa[4] = {qv.x, qv.y, qv.z, qv.w};
            float ka[4] = {kv.x, kv.y, kv.z, kv.w};
#pragma unroll
            for (int i = 0; i < 4; i++)
#pragma unroll
                for (int j = 0; j < 4; j++)
                    s[i][j] += qa[i] * ka[j];
        }

        // scale + additive mask (per key)
        float mk[4];
#pragma unroll
        for (int j = 0; j < 4; j++) mk[j] = maskb[kt + tx * 4 + j];
#pragma unroll
        for (int i = 0; i < 4; i++)
#pragma unroll
            for (int j = 0; j < 4; j++)
                s[i][j] = s[i][j] * scale + mk[j];

        // Online softmax. Row-group = 16 lanes sharing ty (lanes 0-15 / 16-31
        // of a warp), so xor-shuffles with offsets 8..1 stay in-group.
#pragma unroll
        for (int i = 0; i < 4; i++) {
            float tm = fmaxf(fmaxf(s[i][0], s[i][1]), fmaxf(s[i][2], s[i][3]));
#pragma unroll
            for (int off = 8; off >= 1; off >>= 1)
                tm = fmaxf(tm, __shfl_xor_sync(0xffffffffu, tm, off));
            float nm   = fmaxf(m_i[i], tm);
            float corr = __expf(m_i[i] - nm);
            m_i[i] = nm;
            float ts = 0.0f;
#pragma unroll
            for (int j = 0; j < 4; j++) {
                s[i][j] = __expf(s[i][j] - nm);
                ts += s[i][j];
            }
#pragma unroll
            for (int off = 8; off >= 1; off >>= 1)
                ts += __shfl_xor_sync(0xffffffffu, ts, off);
            l_i[i] = l_i[i] * corr + ts;
#pragma unroll
            for (int j = 0; j < 4; j++) o[i][j] *= corr;
        }

        __syncthreads();   // all threads finished reading Kt

        // Store P transposed into the Kt buffer: Pt[key][row]
#pragma unroll
        for (int j = 0; j < 4; j++) {
            float4 pv;
            pv.x = s[0][j]; pv.y = s[1][j]; pv.z = s[2][j]; pv.w = s[3][j];
            *(float4*)(Kt + (tx * 4 + j) * KT_STRIDE + ty * 4) = pv;
        }
        __syncthreads();

        // O += P @ V
#pragma unroll 8
        for (int key = 0; key < 64; key++) {
            float4 pv = *(float4*)(Kt + key * KT_STRIDE + ty * 4);
            float4 vv = *(float4*)(Vs + key * 64 + tx * 4);
            float pa[4] = {pv.x, pv.y, pv.z, pv.w};
            float va[4] = {vv.x, vv.y, vv.z, vv.w};
#pragma unroll
            for (int i = 0; i < 4; i++)
#pragma unroll
                for (int j = 0; j < 4; j++)
                    o[i][j] += pa[i] * va[j];
        }
    }

    // Normalize and write out (same column layout as g_Q)
#pragma unroll
    for (int i = 0; i < 4; i++) {
        float inv = 1.0f / l_i[i];
        float4 ov;
        ov.x = o[i][0] * inv; ov.y = o[i][1] * inv;
        ov.z = o[i][2] * inv; ov.w = o[i][3] * inv;
        *(float4*)&g_A[(m0 + ty * 4 + i) * HIDDEN + h * HEAD_DIM + tx * 4] = ov;
    }
}

// ---------------------------------------------------------------------------
extern "C" void kernel_launch(void* const* d_in, const int* in_sizes, int n_in,
                              void* d_out, int out_size)
{
    const float* x    = (const float*)d_in[0];
    const float* mask = (const float*)d_in[1];
    const float* Wq   = (const float*)d_in[2];
    const float* bq   = (const float*)d_in[3];
    const float* Wk   = (const float*)d_in[4];
    const float* bk   = (const float*)d_in[5];
    const float* Wv   = (const float*)d_in[6];
    const float* bv   = (const float*)d_in[7];
    const float* Wo   = (const float*)d_in[8];
    const float* bo   = (const float*)d_in[9];
    float* out = (float*)d_out;

    float *q, *k, *v, *a;
    cudaGetSymbolAddress((void**)&q, g_Q);
    cudaGetSymbolAddress((void**)&k, g_K);
    cudaGetSymbolAddress((void**)&v, g_V);
    cudaGetSymbolAddress((void**)&a, g_A);

    const int FA_SMEM = (64 * 64 + 64 * KT_STRIDE + 64 * 64) * (int)sizeof(float); // 50176
    cudaFuncSetAttribute((const void*)flash_attn,
                         cudaFuncAttributeMaxDynamicSharedMemorySize, FA_SMEM);

    dim3 blk(256);
    // Q = x @ Wq + bq   [4096,2048]
    gemm_bias<<<dim3(HIDDEN / 128, MTOT / 128), blk>>>(x, Wq, bq, q, MTOT, HIDDEN, HIDDEN);
    // K = x @ Wk + bk   [4096,512]
    gemm_bias<<<dim3(KVSIZE / 128, MTOT / 128), blk>>>(x, Wk, bk, k, MTOT, KVSIZE, HIDDEN);
    // V = x @ Wv + bv
    gemm_bias<<<dim3(KVSIZE / 128, MTOT / 128), blk>>>(x, Wv, bv, v, MTOT, KVSIZE, HIDDEN);
    // Fused attention
    flash_attn<<<dim3(SEQ / BM, HEADS, BATCH), blk, FA_SMEM>>>(mask);
    // out = A @ Wo + bo
    gemm_bias<<<dim3(HIDDEN / 128, MTOT / 128), blk>>>(a, Wo, bo, out, MTOT, HIDDEN, HIDDEN);
}

// round 5
// speedup vs baseline: 2.8663x; 2.8663x over previous
#include <cuda_runtime.h>
#include <cstdint>

#define HIDDEN   2048
#define KVSIZE   512
#define HEADS    32
#define HEAD_DIM 64
#define BATCH    2
#define SEQ      2048
#define MTOT     (BATCH * SEQ)

// Scratch (device globals: allocation inside kernel_launch is forbidden)
__device__ float g_Q[MTOT * HIDDEN];   // [m][h*64+d]
__device__ float g_K[MTOT * KVSIZE];   // [m][kvh*64+d]
__device__ float g_V[MTOT * KVSIZE];
__device__ float g_A[MTOT * HIDDEN];   // attention output, same layout as g_Q

// ---------------------------------------------------------------------------
// tf32 helpers
// ---------------------------------------------------------------------------
__device__ __forceinline__ unsigned f2tf(float f) {
    unsigned u;
    asm("cvt.rna.tf32.f32 %0, %1;" : "=r"(u) : "f"(f));
    return u;
}

__device__ __forceinline__ void mma_tf32(float c[4],
                                         unsigned a0, unsigned a1, unsigned a2, unsigned a3,
                                         unsigned b0, unsigned b1) {
    asm("mma.sync.aligned.m16n8k8.row.col.f32.tf32.tf32.f32 "
        "{%0,%1,%2,%3}, {%4,%5,%6,%7}, {%8,%9}, {%0,%1,%2,%3};"
        : "+f"(c[0]), "+f"(c[1]), "+f"(c[2]), "+f"(c[3])
        : "r"(a0), "r"(a1), "r"(a2), "r"(a3), "r"(b0), "r"(b1));
}

// ---------------------------------------------------------------------------
// C[M,N] = A[M,K] @ B[K,N] + bias[N]   via tf32 tensor-core mma.
// 128x128x32 block tile, 256 threads (8 warps), warp tile 64x32.
// Smem strides 40 / 136 are ≡8 (mod 32) -> all fragment LDS conflict-free.
// ---------------------------------------------------------------------------
#define AST 40
#define BST 136

__global__ __launch_bounds__(256) void gemm_tf32(
    const float* __restrict__ A, const float* __restrict__ B,
    const float* __restrict__ bias, float* __restrict__ C,
    int M, int N, int K)
{
    __shared__ unsigned As[128][AST];  // [m][k], tf32
    __shared__ unsigned Bs[32][BST];   // [k][n], tf32

    const int tid  = threadIdx.x;
    const int lane = tid & 31;
    const int w    = tid >> 5;
    const int lq = lane >> 2, lr = lane & 3;
    const int wm = (w >> 2) * 64;       // 0 or 64
    const int wn = (w & 3) * 32;        // 0,32,64,96
    const int brow = blockIdx.y * 128;
    const int bcol = blockIdx.x * 128;

    float c[4][4][4] = {};              // [mi][ni][frag]

    for (int kt = 0; kt < K; kt += 32) {
        // A tile 128x32, row-major, converted to tf32
#pragma unroll
        for (int i = 0; i < 4; i++) {
            int f = tid + i * 256;
            int r = f >> 3, c4 = (f & 7) << 2;
            float4 v = *(const float4*)&A[(size_t)(brow + r) * K + kt + c4];
            As[r][c4 + 0] = f2tf(v.x); As[r][c4 + 1] = f2tf(v.y);
            As[r][c4 + 2] = f2tf(v.z); As[r][c4 + 3] = f2tf(v.w);
        }
        // B tile 32x128
#pragma unroll
        for (int i = 0; i < 4; i++) {
            int f = tid + i * 256;
            int r = f >> 5, c4 = (f & 31) << 2;
            float4 v = *(const float4*)&B[(size_t)(kt + r) * N + bcol + c4];
            Bs[r][c4 + 0] = f2tf(v.x); Bs[r][c4 + 1] = f2tf(v.y);
            Bs[r][c4 + 2] = f2tf(v.z); Bs[r][c4 + 3] = f2tf(v.w);
        }
        __syncthreads();

#pragma unroll
        for (int kk = 0; kk < 32; kk += 8) {
            unsigned a[4][4], bf[4][2];
#pragma unroll
            for (int mi = 0; mi < 4; mi++) {
                int r0 = wm + mi * 16 + lq;
                a[mi][0] = As[r0][kk + lr];
                a[mi][1] = As[r0 + 8][kk + lr];
                a[mi][2] = As[r0][kk + 4 + lr];
                a[mi][3] = As[r0 + 8][kk + 4 + lr];
            }
#pragma unroll
            for (int ni = 0; ni < 4; ni++) {
                int c0 = wn + ni * 8 + lq;
                bf[ni][0] = Bs[kk + lr][c0];
                bf[ni][1] = Bs[kk + 4 + lr][c0];
            }
#pragma unroll
            for (int mi = 0; mi < 4; mi++)
#pragma unroll
                for (int ni = 0; ni < 4; ni++)
                    mma_tf32(c[mi][ni], a[mi][0], a[mi][1], a[mi][2], a[mi][3],
                             bf[ni][0], bf[ni][1]);
        }
        __syncthreads();
    }

    // Epilogue: bias + store (fragment rows lq / lq+8, cols 2*lr contiguous)
#pragma unroll
    for (int mi = 0; mi < 4; mi++)
#pragma unroll
        for (int ni = 0; ni < 4; ni++) {
            int row = brow + wm + mi * 16 + lq;
            int col = bcol + wn + ni * 8 + 2 * lr;
            float b0 = bias[col], b1 = bias[col + 1];
            float2 o1 = make_float2(c[mi][ni][0] + b0, c[mi][ni][1] + b1);
            float2 o2 = make_float2(c[mi][ni][2] + b0, c[mi][ni][3] + b1);
            *(float2*)&C[(size_t)row * N + col]       = o1;
            *(float2*)&C[(size_t)(row + 8) * N + col] = o2;
        }
}

// ---------------------------------------------------------------------------
// Fused flash attention, tf32 tensor cores.
// Grid: (SEQ/64, HEADS, BATCH). Block: 128 threads = 4 warps.
// Warp w owns query rows [w*16, w*16+16). Q fragments persist in registers.
// Smem: Ks[64][72] (K tile, reused as P tile), Vs[64][72]. 72 ≡ 8 (mod 32)
// makes every fragment access pattern (lane/4)*8 + lane%4 -> conflict-free.
// ---------------------------------------------------------------------------
#define FST 72

__global__ __launch_bounds__(128) void flash_attn_tc(const float* __restrict__ mask)
{
    __shared__ unsigned Ks[64][FST];   // K tile [key][d]; later P tile [q][key]
    __shared__ unsigned Vs[64][FST];   // V tile [key][d]

    const int tid  = threadIdx.x;
    const int lane = tid & 31;
    const int w    = tid >> 5;          // 0..3
    const int lq = lane >> 2, lr = lane & 3;
    const int h   = blockIdx.y;
    const int b   = blockIdx.z;
    const int kvh = h >> 2;
    const int m0  = b * SEQ + blockIdx.x * 64;
    const int q0  = w * 16;
    const float* maskb = mask + b * SEQ;

    // Stage Q tile through Ks (coalesced), convert to tf32
#pragma unroll
    for (int i = 0; i < 8; i++) {
        int f = tid + i * 128;              // 1024 float4 slots
        int r = f >> 4, d4 = (f & 15) << 2;
        float4 v = *(const float4*)&g_Q[(size_t)(m0 + r) * HIDDEN + h * HEAD_DIM + d4];
        Ks[r][d4 + 0] = f2tf(v.x); Ks[r][d4 + 1] = f2tf(v.y);
        Ks[r][d4 + 2] = f2tf(v.z); Ks[r][d4 + 3] = f2tf(v.w);
    }
    __syncthreads();

    // Q fragments in registers: 8 k-chunks of 8 dims
    unsigned qf[8][4];
#pragma unroll
    for (int ki = 0; ki < 8; ki++) {
        qf[ki][0] = Ks[q0 + lq][ki * 8 + lr];
        qf[ki][1] = Ks[q0 + 8 + lq][ki * 8 + lr];
        qf[ki][2] = Ks[q0 + lq][ki * 8 + 4 + lr];
        qf[ki][3] = Ks[q0 + 8 + lq][ki * 8 + 4 + lr];
    }

    float m1 = -1e30f, m2 = -1e30f, l1 = 0.f, l2 = 0.f;
    float o[8][4] = {};                  // O accum: [d-tile][frag]

    for (int kt = 0; kt < SEQ; kt += 64) {
        __syncthreads();                 // prior PV (and Q frag reads) done

        // Load K and V tiles (tf32)
#pragma unroll
        for (int i = 0; i < 8; i++) {
            int f = tid + i * 128;
            int key = f >> 4, d4 = (f & 15) << 2;
            size_t gidx = (size_t)(b * SEQ + kt + key) * KVSIZE + kvh * HEAD_DIM + d4;
            float4 kv = *(const float4*)&g_K[gidx];
            float4 vv = *(const float4*)&g_V[gidx];
            Ks[key][d4 + 0] = f2tf(kv.x); Ks[key][d4 + 1] = f2tf(kv.y);
            Ks[key][d4 + 2] = f2tf(kv.z); Ks[key][d4 + 3] = f2tf(kv.w);
            Vs[key][d4 + 0] = f2tf(vv.x); Vs[key][d4 + 1] = f2tf(vv.y);
            Vs[key][d4 + 2] = f2tf(vv.z); Vs[key][d4 + 3] = f2tf(vv.w);
        }
        __syncthreads();

        // S = Q K^T   (warp: 16 q-rows x 64 keys = 8 n-tiles)
        float s[8][4] = {};
#pragma unroll
        for (int ki = 0; ki < 8; ki++) {
#pragma unroll
            for (int ni = 0; ni < 8; ni++) {
                unsigned b0 = Ks[ni * 8 + lq][ki * 8 + lr];
                unsigned b1 = Ks[ni * 8 + lq][ki * 8 + 4 + lr];
                mma_tf32(s[ni], qf[ki][0], qf[ki][1], qf[ki][2], qf[ki][3], b0, b1);
            }
        }

        // scale + mask (cols 2*lr, 2*lr+1 contiguous -> float2 loads)
#pragma unroll
        for (int ni = 0; ni < 8; ni++) {
            float2 mv = *(const float2*)&maskb[kt + ni * 8 + 2 * lr];
            s[ni][0] = s[ni][0] * 0.125f + mv.x;
            s[ni][1] = s[ni][1] * 0.125f + mv.y;
            s[ni][2] = s[ni][2] * 0.125f + mv.x;
            s[ni][3] = s[ni][3] * 0.125f + mv.y;
        }

        // Online softmax. Row r1 = lq (frags 0,1), r2 = lq+8 (frags 2,3).
        // 4-lane row groups -> xor 1,2 shuffles.
        float tm1 = -1e30f, tm2 = -1e30f;
#pragma unroll
        for (int ni = 0; ni < 8; ni++) {
            tm1 = fmaxf(tm1, fmaxf(s[ni][0], s[ni][1]));
            tm2 = fmaxf(tm2, fmaxf(s[ni][2], s[ni][3]));
        }
        tm1 = fmaxf(tm1, __shfl_xor_sync(0xffffffffu, tm1, 1));
        tm1 = fmaxf(tm1, __shfl_xor_sync(0xffffffffu, tm1, 2));
        tm2 = fmaxf(tm2, __shfl_xor_sync(0xffffffffu, tm2, 1));
        tm2 = fmaxf(tm2, __shfl_xor_sync(0xffffffffu, tm2, 2));
        float nm1 = fmaxf(m1, tm1), nm2 = fmaxf(m2, tm2);
        float corr1 = __expf(m1 - nm1), corr2 = __expf(m2 - nm2);
        m1 = nm1; m2 = nm2;
        float ts1 = 0.f, ts2 = 0.f;
#pragma unroll
        for (int ni = 0; ni < 8; ni++) {
            s[ni][0] = __expf(s[ni][0] - nm1); ts1 += s[ni][0];
            s[ni][1] = __expf(s[ni][1] - nm1); ts1 += s[ni][1];
            s[ni][2] = __expf(s[ni][2] - nm2); ts2 += s[ni][2];
            s[ni][3] = __expf(s[ni][3] - nm2); ts2 += s[ni][3];
        }
        ts1 += __shfl_xor_sync(0xffffffffu, ts1, 1);
        ts1 += __shfl_xor_sync(0xffffffffu, ts1, 2);
        ts2 += __shfl_xor_sync(0xffffffffu, ts2, 1);
        ts2 += __shfl_xor_sync(0xffffffffu, ts2, 2);
        l1 = l1 * corr1 + ts1;
        l2 = l2 * corr2 + ts2;
#pragma unroll
        for (int di = 0; di < 8; di++) {
            o[di][0] *= corr1; o[di][1] *= corr1;
            o[di][2] *= corr2; o[di][3] *= corr2;
        }

        __syncthreads();                 // all warps finished reading Ks

        // Store P (tf32) into Ks as [q][key]; uint2 -> STS.64, conflict-free
#pragma unroll
        for (int ni = 0; ni < 8; ni++) {
            int col = ni * 8 + 2 * lr;
            *(uint2*)&Ks[q0 + lq][col]     = make_uint2(f2tf(s[ni][0]), f2tf(s[ni][1]));
            *(uint2*)&Ks[q0 + 8 + lq][col] = make_uint2(f2tf(s[ni][2]), f2tf(s[ni][3]));
        }
        __syncthreads();

        // O += P @ V   (m16 x k64(keys) x n64(dims))
#pragma unroll
        for (int ki = 0; ki < 8; ki++) {
            unsigned pa0 = Ks[q0 + lq][ki * 8 + lr];
            unsigned pa1 = Ks[q0 + 8 + lq][ki * 8 + lr];
            unsigned pa2 = Ks[q0 + lq][ki * 8 + 4 + lr];
            unsigned pa3 = Ks[q0 + 8 + lq][ki * 8 + 4 + lr];
#pragma unroll
            for (int di = 0; di < 8; di++) {
                unsigned b0 = Vs[ki * 8 + lr][di * 8 + lq];
                unsigned b1 = Vs[ki * 8 + 4 + lr][di * 8 + lq];
                mma_tf32(o[di], pa0, pa1, pa2, pa3, b0, b1);
            }
        }
    }

    // Normalize + write A (same [m][h*64+d] layout as g_Q)
    float inv1 = 1.0f / l1, inv2 = 1.0f / l2;
#pragma unroll
    for (int di = 0; di < 8; di++) {
        int col  = h * HEAD_DIM + di * 8 + 2 * lr;
        int row1 = m0 + q0 + lq;
        *(float2*)&g_A[(size_t)row1 * HIDDEN + col] =
            make_float2(o[di][0] * inv1, o[di][1] * inv1);
        *(float2*)&g_A[(size_t)(row1 + 8) * HIDDEN + col] =
            make_float2(o[di][2] * inv2, o[di][3] * inv2);
    }
}

// ---------------------------------------------------------------------------
extern "C" void kernel_launch(void* const* d_in, const int* in_sizes, int n_in,
                              void* d_out, int out_size)
{
    const float* x    = (const float*)d_in[0];
    const float* mask = (const float*)d_in[1];
    const float* Wq   = (const float*)d_in[2];
    const float* bq   = (const float*)d_in[3];
    const float* Wk   = (const float*)d_in[4];
    const float* bk   = (const float*)d_in[5];
    const float* Wv   = (const float*)d_in[6];
    const float* bv   = (const float*)d_in[7];
    const float* Wo   = (const float*)d_in[8];
    const float* bo   = (const float*)d_in[9];
    float* out = (float*)d_out;

    float *q, *k, *v, *a;
    cudaGetSymbolAddress((void**)&q, g_Q);
    cudaGetSymbolAddress((void**)&k, g_K);
    cudaGetSymbolAddress((void**)&v, g_V);
    cudaGetSymbolAddress((void**)&a, g_A);

    dim3 blk(256);
    // Q = x @ Wq + bq   [4096,2048]
    gemm_tf32<<<dim3(HIDDEN / 128, MTOT / 128), blk>>>(x, Wq, bq, q, MTOT, HIDDEN, HIDDEN);
    // K = x @ Wk + bk   [4096,512]
    gemm_tf32<<<dim3(KVSIZE / 128, MTOT / 128), blk>>>(x, Wk, bk, k, MTOT, KVSIZE, HIDDEN);
    // V = x @ Wv + bv
    gemm_tf32<<<dim3(KVSIZE / 128, MTOT / 128), blk>>>(x, Wv, bv, v, MTOT, KVSIZE, HIDDEN);
    // Fused attention (tensor cores)
    flash_attn_tc<<<dim3(SEQ / 64, HEADS, BATCH), dim3(128)>>>(mask);
    // out = A @ Wo + bo
    gemm_tf32<<<dim3(HIDDEN / 128, MTOT / 128), blk>>>(a, Wo, bo, out, MTOT, HIDDEN, HIDDEN);
}

// round 6
// speedup vs baseline: 2.8668x; 1.0002x over previous
#include <cuda_runtime.h>
#include <cstdint>

#define HIDDEN   2048
#define KVSIZE   512
#define HEADS    32
#define HEAD_DIM 64
#define BATCH    2
#define SEQ      2048
#define MTOT     (BATCH * SEQ)

// Scratch (device globals: allocation inside kernel_launch is forbidden)
__device__ float g_Q[MTOT * HIDDEN];   // [m][h*64+d]
__device__ float g_K[MTOT * KVSIZE];   // [m][kvh*64+d]
__device__ float g_V[MTOT * KVSIZE];
__device__ float g_A[MTOT * HIDDEN];   // attention output, same layout as g_Q

// ---------------------------------------------------------------------------
// tf32 helpers
// ---------------------------------------------------------------------------
__device__ __forceinline__ unsigned f2tf(float f) {
    unsigned u;
    asm("cvt.rna.tf32.f32 %0, %1;" : "=r"(u) : "f"(f));
    return u;
}

__device__ __forceinline__ void mma_tf32(float c[4],
                                         unsigned a0, unsigned a1, unsigned a2, unsigned a3,
                                         unsigned b0, unsigned b1) {
    asm("mma.sync.aligned.m16n8k8.row.col.f32.tf32.tf32.f32 "
        "{%0,%1,%2,%3}, {%4,%5,%6,%7}, {%8,%9}, {%0,%1,%2,%3};"
        : "+f"(c[0]), "+f"(c[1]), "+f"(c[2]), "+f"(c[3])
        : "r"(a0), "r"(a1), "r"(a2), "r"(a3), "r"(b0), "r"(b1));
}

// ---------------------------------------------------------------------------
// C[M,N] = A[M,K] @ B[K,N] + bias[N]   via tf32 tensor-core mma.
// 128x128x32 block tile, 256 threads (8 warps), warp tile 64x32.
// Smem strides 40 / 136 are ≡8 (mod 32) -> all fragment LDS conflict-free.
// ---------------------------------------------------------------------------
#define AST 40
#define BST 136

__global__ __launch_bounds__(256) void gemm_tf32(
    const float* __restrict__ A, const float* __restrict__ B,
    const float* __restrict__ bias, float* __restrict__ C,
    int M, int N, int K)
{
    __shared__ unsigned As[128][AST];  // [m][k], tf32
    __shared__ unsigned Bs[32][BST];   // [k][n], tf32

    const int tid  = threadIdx.x;
    const int lane = tid & 31;
    const int w    = tid >> 5;
    const int lq = lane >> 2, lr = lane & 3;
    const int wm = (w >> 2) * 64;       // 0 or 64
    const int wn = (w & 3) * 32;        // 0,32,64,96
    const int brow = blockIdx.y * 128;
    const int bcol = blockIdx.x * 128;

    float c[4][4][4] = {};              // [mi][ni][frag]

    for (int kt = 0; kt < K; kt += 32) {
        // A tile 128x32, row-major, converted to tf32
#pragma unroll
        for (int i = 0; i < 4; i++) {
            int f = tid + i * 256;
            int r = f >> 3, c4 = (f & 7) << 2;
            float4 v = *(const float4*)&A[(size_t)(brow + r) * K + kt + c4];
            As[r][c4 + 0] = f2tf(v.x); As[r][c4 + 1] = f2tf(v.y);
            As[r][c4 + 2] = f2tf(v.z); As[r][c4 + 3] = f2tf(v.w);
        }
        // B tile 32x128
#pragma unroll
        for (int i = 0; i < 4; i++) {
            int f = tid + i * 256;
            int r = f >> 5, c4 = (f & 31) << 2;
            float4 v = *(const float4*)&B[(size_t)(kt + r) * N + bcol + c4];
            Bs[r][c4 + 0] = f2tf(v.x); Bs[r][c4 + 1] = f2tf(v.y);
            Bs[r][c4 + 2] = f2tf(v.z); Bs[r][c4 + 3] = f2tf(v.w);
        }
        __syncthreads();

#pragma unroll
        for (int kk = 0; kk < 32; kk += 8) {
            unsigned a[4][4], bf[4][2];
#pragma unroll
            for (int mi = 0; mi < 4; mi++) {
                int r0 = wm + mi * 16 + lq;
                a[mi][0] = As[r0][kk + lr];
                a[mi][1] = As[r0 + 8][kk + lr];
                a[mi][2] = As[r0][kk + 4 + lr];
                a[mi][3] = As[r0 + 8][kk + 4 + lr];
            }
#pragma unroll
            for (int ni = 0; ni < 4; ni++) {
                int c0 = wn + ni * 8 + lq;
                bf[ni][0] = Bs[kk + lr][c0];
                bf[ni][1] = Bs[kk + 4 + lr][c0];
            }
#pragma unroll
            for (int mi = 0; mi < 4; mi++)
#pragma unroll
                for (int ni = 0; ni < 4; ni++)
                    mma_tf32(c[mi][ni], a[mi][0], a[mi][1], a[mi][2], a[mi][3],
                             bf[ni][0], bf[ni][1]);
        }
        __syncthreads();
    }

    // Epilogue: bias + store (fragment rows lq / lq+8, cols 2*lr contiguous)
#pragma unroll
    for (int mi = 0; mi < 4; mi++)
#pragma unroll
        for (int ni = 0; ni < 4; ni++) {
            int row = brow + wm + mi * 16 + lq;
            int col = bcol + wn + ni * 8 + 2 * lr;
            float b0 = bias[col], b1 = bias[col + 1];
            float2 o1 = make_float2(c[mi][ni][0] + b0, c[mi][ni][1] + b1);
            float2 o2 = make_float2(c[mi][ni][2] + b0, c[mi][ni][3] + b1);
            *(float2*)&C[(size_t)row * N + col]       = o1;
            *(float2*)&C[(size_t)(row + 8) * N + col] = o2;
        }
}

// ---------------------------------------------------------------------------
// Fused flash attention, tf32 tensor cores.
// Grid: (SEQ/64, HEADS, BATCH). Block: 128 threads = 4 warps.
// Warp w owns query rows [w*16, w*16+16). Q fragments persist in registers.
// Smem: Ks[64][72] (K tile, reused as P tile), Vs[64][72]. 72 ≡ 8 (mod 32)
// makes every fragment access pattern (lane/4)*8 + lane%4 -> conflict-free.
// ---------------------------------------------------------------------------
#define FST 72

__global__ __launch_bounds__(128) void flash_attn_tc(const float* __restrict__ mask)
{
    __shared__ unsigned Ks[64][FST];   // K tile [key][d]; later P tile [q][key]
    __shared__ unsigned Vs[64][FST];   // V tile [key][d]

    const int tid  = threadIdx.x;
    const int lane = tid & 31;
    const int w    = tid >> 5;          // 0..3
    const int lq = lane >> 2, lr = lane & 3;
    const int h   = blockIdx.y;
    const int b   = blockIdx.z;
    const int kvh = h >> 2;
    const int m0  = b * SEQ + blockIdx.x * 64;
    const int q0  = w * 16;
    const float* maskb = mask + b * SEQ;

    // Stage Q tile through Ks (coalesced), convert to tf32
#pragma unroll
    for (int i = 0; i < 8; i++) {
        int f = tid + i * 128;              // 1024 float4 slots
        int r = f >> 4, d4 = (f & 15) << 2;
        float4 v = *(const float4*)&g_Q[(size_t)(m0 + r) * HIDDEN + h * HEAD_DIM + d4];
        Ks[r][d4 + 0] = f2tf(v.x); Ks[r][d4 + 1] = f2tf(v.y);
        Ks[r][d4 + 2] = f2tf(v.z); Ks[r][d4 + 3] = f2tf(v.w);
    }
    __syncthreads();

    // Q fragments in registers: 8 k-chunks of 8 dims
    unsigned qf[8][4];
#pragma unroll
    for (int ki = 0; ki < 8; ki++) {
        qf[ki][0] = Ks[q0 + lq][ki * 8 + lr];
        qf[ki][1] = Ks[q0 + 8 + lq][ki * 8 + lr];
        qf[ki][2] = Ks[q0 + lq][ki * 8 + 4 + lr];
        qf[ki][3] = Ks[q0 + 8 + lq][ki * 8 + 4 + lr];
    }

    float m1 = -1e30f, m2 = -1e30f, l1 = 0.f, l2 = 0.f;
    float o[8][4] = {};                  // O accum: [d-tile][frag]

    for (int kt = 0; kt < SEQ; kt += 64) {
        __syncthreads();                 // prior PV (and Q frag reads) done

        // Load K and V tiles (tf32)
#pragma unroll
        for (int i = 0; i < 8; i++) {
            int f = tid + i * 128;
            int key = f >> 4, d4 = (f & 15) << 2;
            size_t gidx = (size_t)(b * SEQ + kt + key) * KVSIZE + kvh * HEAD_DIM + d4;
            float4 kv = *(const float4*)&g_K[gidx];
            float4 vv = *(const float4*)&g_V[gidx];
            Ks[key][d4 + 0] = f2tf(kv.x); Ks[key][d4 + 1] = f2tf(kv.y);
            Ks[key][d4 + 2] = f2tf(kv.z); Ks[key][d4 + 3] = f2tf(kv.w);
            Vs[key][d4 + 0] = f2tf(vv.x); Vs[key][d4 + 1] = f2tf(vv.y);
            Vs[key][d4 + 2] = f2tf(vv.z); Vs[key][d4 + 3] = f2tf(vv.w);
        }
        __syncthreads();

        // S = Q K^T   (warp: 16 q-rows x 64 keys = 8 n-tiles)
        float s[8][4] = {};
#pragma unroll
        for (int ki = 0; ki < 8; ki++) {
#pragma unroll
            for (int ni = 0; ni < 8; ni++) {
                unsigned b0 = Ks[ni * 8 + lq][ki * 8 + lr];
                unsigned b1 = Ks[ni * 8 + lq][ki * 8 + 4 + lr];
                mma_tf32(s[ni], qf[ki][0], qf[ki][1], qf[ki][2], qf[ki][3], b0, b1);
            }
        }

        // scale + mask (cols 2*lr, 2*lr+1 contiguous -> float2 loads)
#pragma unroll
        for (int ni = 0; ni < 8; ni++) {
            float2 mv = *(const float2*)&maskb[kt + ni * 8 + 2 * lr];
            s[ni][0] = s[ni][0] * 0.125f + mv.x;
            s[ni][1] = s[ni][1] * 0.125f + mv.y;
            s[ni][2] = s[ni][2] * 0.125f + mv.x;
            s[ni][3] = s[ni][3] * 0.125f + mv.y;
        }

        // Online softmax. Row r1 = lq (frags 0,1), r2 = lq+8 (frags 2,3).
        // 4-lane row groups -> xor 1,2 shuffles.
        float tm1 = -1e30f, tm2 = -1e30f;
#pragma unroll
        for (int ni = 0; ni < 8; ni++) {
            tm1 = fmaxf(tm1, fmaxf(s[ni][0], s[ni][1]));
            tm2 = fmaxf(tm2, fmaxf(s[ni][2], s[ni][3]));
        }
        tm1 = fmaxf(tm1, __shfl_xor_sync(0xffffffffu, tm1, 1));
        tm1 = fmaxf(tm1, __shfl_xor_sync(0xffffffffu, tm1, 2));
        tm2 = fmaxf(tm2, __shfl_xor_sync(0xffffffffu, tm2, 1));
        tm2 = fmaxf(tm2, __shfl_xor_sync(0xffffffffu, tm2, 2));
        float nm1 = fmaxf(m1, tm1), nm2 = fmaxf(m2, tm2);
        float corr1 = __expf(m1 - nm1), corr2 = __expf(m2 - nm2);
        m1 = nm1; m2 = nm2;
        float ts1 = 0.f, ts2 = 0.f;
#pragma unroll
        for (int ni = 0; ni < 8; ni++) {
            s[ni][0] = __expf(s[ni][0] - nm1); ts1 += s[ni][0];
            s[ni][1] = __expf(s[ni][1] - nm1); ts1 += s[ni][1];
            s[ni][2] = __expf(s[ni][2] - nm2); ts2 += s[ni][2];
            s[ni][3] = __expf(s[ni][3] - nm2); ts2 += s[ni][3];
        }
        ts1 += __shfl_xor_sync(0xffffffffu, ts1, 1);
        ts1 += __shfl_xor_sync(0xffffffffu, ts1, 2);
        ts2 += __shfl_xor_sync(0xffffffffu, ts2, 1);
        ts2 += __shfl_xor_sync(0xffffffffu, ts2, 2);
        l1 = l1 * corr1 + ts1;
        l2 = l2 * corr2 + ts2;
#pragma unroll
        for (int di = 0; di < 8; di++) {
            o[di][0] *= corr1; o[di][1] *= corr1;
            o[di][2] *= corr2; o[di][3] *= corr2;
        }

        __syncthreads();                 // all warps finished reading Ks

        // Store P (tf32) into Ks as [q][key]; uint2 -> STS.64, conflict-free
#pragma unroll
        for (int ni = 0; ni < 8; ni++) {
            int col = ni * 8 + 2 * lr;
            *(uint2*)&Ks[q0 + lq][col]     = make_uint2(f2tf(s[ni][0]), f2tf(s[ni][1]));
            *(uint2*)&Ks[q0 + 8 + lq][col] = make_uint2(f2tf(s[ni][2]), f2tf(s[ni][3]));
        }
        __syncthreads();

        // O += P @ V   (m16 x k64(keys) x n64(dims))
#pragma unroll
        for (int ki = 0; ki < 8; ki++) {
            unsigned pa0 = Ks[q0 + lq][ki * 8 + lr];
            unsigned pa1 = Ks[q0 + 8 + lq][ki * 8 + lr];
            unsigned pa2 = Ks[q0 + lq][ki * 8 + 4 + lr];
            unsigned pa3 = Ks[q0 + 8 + lq][ki * 8 + 4 + lr];
#pragma unroll
            for (int di = 0; di < 8; di++) {
                unsigned b0 = Vs[ki * 8 + lr][di * 8 + lq];
                unsigned b1 = Vs[ki * 8 + 4 + lr][di * 8 + lq];
                mma_tf32(o[di], pa0, pa1, pa2, pa3, b0, b1);
            }
        }
    }

    // Normalize + write A (same [m][h*64+d] layout as g_Q)
    float inv1 = 1.0f / l1, inv2 = 1.0f / l2;
#pragma unroll
    for (int di = 0; di < 8; di++) {
        int col  = h * HEAD_DIM + di * 8 + 2 * lr;
        int row1 = m0 + q0 + lq;
        *(float2*)&g_A[(size_t)row1 * HIDDEN + col] =
            make_float2(o[di][0] * inv1, o[di][1] * inv1);
        *(float2*)&g_A[(size_t)(row1 + 8) * HIDDEN + col] =
            make_float2(o[di][2] * inv2, o[di][3] * inv2);
    }
}

// ---------------------------------------------------------------------------
extern "C" void kernel_launch(void* const* d_in, const int* in_sizes, int n_in,
                              void* d_out, int out_size)
{
    const float* x    = (const float*)d_in[0];
    const float* mask = (const float*)d_in[1];
    const float* Wq   = (const float*)d_in[2];
    const float* bq   = (const float*)d_in[3];
    const float* Wk   = (const float*)d_in[4];
    const float* bk   = (const float*)d_in[5];
    const float* Wv   = (const float*)d_in[6];
    const float* bv   = (const float*)d_in[7];
    const float* Wo   = (const float*)d_in[8];
    const float* bo   = (const float*)d_in[9];
    float* out = (float*)d_out;

    float *q, *k, *v, *a;
    cudaGetSymbolAddress((void**)&q, g_Q);
    cudaGetSymbolAddress((void**)&k, g_K);
    cudaGetSymbolAddress((void**)&v, g_V);
    cudaGetSymbolAddress((void**)&a, g_A);

    dim3 blk(256);
    // Q = x @ Wq + bq   [4096,2048]
    gemm_tf32<<<dim3(HIDDEN / 128, MTOT / 128), blk>>>(x, Wq, bq, q, MTOT, HIDDEN, HIDDEN);
    // K = x @ Wk + bk   [4096,512]
    gemm_tf32<<<dim3(KVSIZE / 128, MTOT / 128), blk>>>(x, Wk, bk, k, MTOT, KVSIZE, HIDDEN);
    // V = x @ Wv + bv
    gemm_tf32<<<dim3(KVSIZE / 128, MTOT / 128), blk>>>(x, Wv, bv, v, MTOT, KVSIZE, HIDDEN);
    // Fused attention (tensor cores)
    flash_attn_tc<<<dim3(SEQ / 64, HEADS, BATCH), dim3(128)>>>(mask);
    // out = A @ Wo + bo
    gemm_tf32<<<dim3(HIDDEN / 128, MTOT / 128), blk>>>(a, Wo, bo, out, MTOT, HIDDEN, HIDDEN);
}

// round 7
// speedup vs baseline: 3.4256x; 1.1949x over previous
#include <cuda_runtime.h>
#include <cuda_fp16.h>
#include <cstdint>

#define HIDDEN   2048
#define KVSIZE   512
#define HEADS    32
#define HEAD_DIM 64
#define BATCH    2
#define SEQ      2048
#define MTOT     (BATCH * SEQ)

// Scratch (device globals: allocation inside kernel_launch is forbidden)
__device__ float g_Q[MTOT * HIDDEN];   // [m][h*64+d]
__device__ float g_K[MTOT * KVSIZE];   // [m][kvh*64+d]
__device__ float g_V[MTOT * KVSIZE];   // TRANSPOSED: [(b*8+kvh)*64+d][seq]
__device__ float g_A[MTOT * HIDDEN];   // attention output, same layout as g_Q

// ---------------------------------------------------------------------------
// helpers
// ---------------------------------------------------------------------------
__device__ __forceinline__ unsigned f2tf(float f) {
    unsigned u;
    asm("cvt.rna.tf32.f32 %0, %1;" : "=r"(u) : "f"(f));
    return u;
}
// pack two fp32 into a half2 word: low half = lo, high half = hi
__device__ __forceinline__ unsigned h2pack(float lo, float hi) {
    unsigned r;
    asm("cvt.rn.f16x2.f32 %0, %1, %2;" : "=r"(r) : "f"(hi), "f"(lo));
    return r;
}
__device__ __forceinline__ void mma_tf32(float c[4],
                                         unsigned a0, unsigned a1, unsigned a2, unsigned a3,
                                         unsigned b0, unsigned b1) {
    asm("mma.sync.aligned.m16n8k8.row.col.f32.tf32.tf32.f32 "
        "{%0,%1,%2,%3}, {%4,%5,%6,%7}, {%8,%9}, {%0,%1,%2,%3};"
        : "+f"(c[0]), "+f"(c[1]), "+f"(c[2]), "+f"(c[3])
        : "r"(a0), "r"(a1), "r"(a2), "r"(a3), "r"(b0), "r"(b1));
}
__device__ __forceinline__ void mma_f16(float c[4],
                                        unsigned a0, unsigned a1, unsigned a2, unsigned a3,
                                        unsigned b0, unsigned b1) {
    asm("mma.sync.aligned.m16n8k16.row.col.f32.f16.f16.f32 "
        "{%0,%1,%2,%3}, {%4,%5,%6,%7}, {%8,%9}, {%0,%1,%2,%3};"
        : "+f"(c[0]), "+f"(c[1]), "+f"(c[2]), "+f"(c[3])
        : "r"(a0), "r"(a1), "r"(a2), "r"(a3), "r"(b0), "r"(b1));
}

// ---------------------------------------------------------------------------
// C[M,N] = A[M,K] @ B[K,N] + bias[N]   via tf32 tensor-core mma.
// 128x128x32 block tile, 256 threads (8 warps), warp tile 64x32.
// transV != 0: scatter-store result transposed into g_V layout
// [(b*8 + kvh)*64 + d][seq]  (row m -> b = m>>11, seq = m&2047; col -> kvh,d).
// ---------------------------------------------------------------------------
#define AST 40
#define BST 136

__global__ __launch_bounds__(256) void gemm_tf32(
    const float* __restrict__ A, const float* __restrict__ B,
    const float* __restrict__ bias, float* __restrict__ C,
    int M, int N, int K, int transV)
{
    __shared__ unsigned As[128][AST];  // [m][k], tf32
    __shared__ unsigned Bs[32][BST];   // [k][n], tf32

    const int tid  = threadIdx.x;
    const int lane = tid & 31;
    const int w    = tid >> 5;
    const int lq = lane >> 2, lr = lane & 3;
    const int wm = (w >> 2) * 64;
    const int wn = (w & 3) * 32;
    const int brow = blockIdx.y * 128;
    const int bcol = blockIdx.x * 128;

    float c[4][4][4] = {};

    for (int kt = 0; kt < K; kt += 32) {
#pragma unroll
        for (int i = 0; i < 4; i++) {
            int f = tid + i * 256;
            int r = f >> 3, c4 = (f & 7) << 2;
            float4 v = *(const float4*)&A[(size_t)(brow + r) * K + kt + c4];
            As[r][c4 + 0] = f2tf(v.x); As[r][c4 + 1] = f2tf(v.y);
            As[r][c4 + 2] = f2tf(v.z); As[r][c4 + 3] = f2tf(v.w);
        }
#pragma unroll
        for (int i = 0; i < 4; i++) {
            int f = tid + i * 256;
            int r = f >> 5, c4 = (f & 31) << 2;
            float4 v = *(const float4*)&B[(size_t)(kt + r) * N + bcol + c4];
            Bs[r][c4 + 0] = f2tf(v.x); Bs[r][c4 + 1] = f2tf(v.y);
            Bs[r][c4 + 2] = f2tf(v.z); Bs[r][c4 + 3] = f2tf(v.w);
        }
        __syncthreads();

#pragma unroll
        for (int kk = 0; kk < 32; kk += 8) {
            unsigned a[4][4], bf[4][2];
#pragma unroll
            for (int mi = 0; mi < 4; mi++) {
                int r0 = wm + mi * 16 + lq;
                a[mi][0] = As[r0][kk + lr];
                a[mi][1] = As[r0 + 8][kk + lr];
                a[mi][2] = As[r0][kk + 4 + lr];
                a[mi][3] = As[r0 + 8][kk + 4 + lr];
            }
#pragma unroll
            for (int ni = 0; ni < 4; ni++) {
                int c0 = wn + ni * 8 + lq;
                bf[ni][0] = Bs[kk + lr][c0];
                bf[ni][1] = Bs[kk + 4 + lr][c0];
            }
#pragma unroll
            for (int mi = 0; mi < 4; mi++)
#pragma unroll
                for (int ni = 0; ni < 4; ni++)
                    mma_tf32(c[mi][ni], a[mi][0], a[mi][1], a[mi][2], a[mi][3],
                             bf[ni][0], bf[ni][1]);
        }
        __syncthreads();
    }

    if (!transV) {
#pragma unroll
        for (int mi = 0; mi < 4; mi++)
#pragma unroll
            for (int ni = 0; ni < 4; ni++) {
                int row = brow + wm + mi * 16 + lq;
                int col = bcol + wn + ni * 8 + 2 * lr;
                float b0 = bias[col], b1 = bias[col + 1];
                *(float2*)&C[(size_t)row * N + col] =
                    make_float2(c[mi][ni][0] + b0, c[mi][ni][1] + b1);
                *(float2*)&C[(size_t)(row + 8) * N + col] =
                    make_float2(c[mi][ni][2] + b0, c[mi][ni][3] + b1);
            }
    } else {
        // transposed scatter for g_V: col never crosses a 64-boundary here
        // (wn%64 + ni*8 + 2*lr + 1 <= 63), so (kvh, d) and (kvh, d+1).
#pragma unroll
        for (int mi = 0; mi < 4; mi++)
#pragma unroll
            for (int ni = 0; ni < 4; ni++) {
                int row = brow + wm + mi * 16 + lq;       // m
                int col = bcol + wn + ni * 8 + 2 * lr;    // kvh*64 + d
                float b0 = bias[col], b1 = bias[col + 1];
                size_t base0 = ((size_t)((row >> 11) * 8) * 64 + col) * SEQ;
                int seq0 = row & 2047;
                C[base0 + seq0]       = c[mi][ni][0] + b0;
                C[base0 + SEQ + seq0] = c[mi][ni][1] + b1;
                int r8 = row + 8;
                size_t base1 = ((size_t)((r8 >> 11) * 8) * 64 + col) * SEQ;
                int seq1 = r8 & 2047;
                C[base1 + seq1]       = c[mi][ni][2] + b0;
                C[base1 + SEQ + seq1] = c[mi][ni][3] + b1;
            }
    }
}

// ---------------------------------------------------------------------------
// Fused flash attention, fp16 tensor cores (m16n8k16), online softmax.
// Grid: (SEQ/64, HEADS, BATCH). Block: 128 threads = 4 warps.
// Warp w owns q-rows [w*16, w*16+16). Q pre-scaled by 1/8, frags in regs.
// Smem word tiles, pitch 36 words (=72 halves, ≡4 mod 32 -> pattern
// 4*lq + lr is conflict-free for every fragment access):
//   Qw[64][36]  Q tile [q][d]      (half2 per word)
//   Kw[64][36]  K tile [key][d]
//   Vw[64][36]  V tile [d][key]    (fed from pre-transposed g_V)
// P never touches smem: S C-fragments are re-packed (cvt.f16x2) directly
// into PV A-fragments (FA2 layout identity).
// ---------------------------------------------------------------------------
__global__ __launch_bounds__(128) void flash_fp16(const float* __restrict__ mask)
{
    __shared__ unsigned Qw[64][36];
    __shared__ unsigned Kw[64][36];
    __shared__ unsigned Vw[64][36];

    const int tid  = threadIdx.x;
    const int lane = tid & 31;
    const int w    = tid >> 5;
    const int lq = lane >> 2, lr = lane & 3;
    const int h   = blockIdx.y;
    const int b   = blockIdx.z;
    const int kvh = h >> 2;
    const int m0  = b * SEQ + blockIdx.x * 64;
    const int q0  = w * 16;
    const float* maskb = mask + b * SEQ;
    const float* Vt = g_V + (size_t)(b * 8 + kvh) * 64 * SEQ;  // [d][seq]

    // Q tile, pre-scaled by 1/sqrt(64) (exact), packed to half2
#pragma unroll
    for (int i = 0; i < 8; i++) {
        int f = i * 128 + tid;                 // 1024 float4 slots
        int r = f >> 4, d4 = (f & 15) << 2;
        float4 v = *(const float4*)&g_Q[(size_t)(m0 + r) * HIDDEN + h * HEAD_DIM + d4];
        *(uint2*)&Qw[r][d4 >> 1] =
            make_uint2(h2pack(v.x * 0.125f, v.y * 0.125f),
                       h2pack(v.z * 0.125f, v.w * 0.125f));
    }
    __syncthreads();

    // Q A-fragments: 4 k-chunks of 16 dims
    unsigned qf[4][4];
#pragma unroll
    for (int kc = 0; kc < 4; kc++) {
        qf[kc][0] = Qw[q0 + lq][kc * 8 + lr];
        qf[kc][1] = Qw[q0 + 8 + lq][kc * 8 + lr];
        qf[kc][2] = Qw[q0 + lq][kc * 8 + 4 + lr];
        qf[kc][3] = Qw[q0 + 8 + lq][kc * 8 + 4 + lr];
    }

    float m1 = -1e30f, m2 = -1e30f, l1 = 0.f, l2 = 0.f;
    float o[8][4] = {};                        // O accum [d-octet][frag]

    for (int kt = 0; kt < SEQ; kt += 64) {
        __syncthreads();                       // prior tile's Kw/Vw reads done

        // K tile [key][d] and V tile [d][key] (V global is pre-transposed)
#pragma unroll
        for (int i = 0; i < 8; i++) {
            int f = i * 128 + tid;
            int r = f >> 4, c4 = (f & 15) << 2;
            float4 kv = *(const float4*)&g_K[(size_t)(b * SEQ + kt + r) * KVSIZE + kvh * 64 + c4];
            *(uint2*)&Kw[r][c4 >> 1] =
                make_uint2(h2pack(kv.x, kv.y), h2pack(kv.z, kv.w));
            float4 vv = *(const float4*)&Vt[(size_t)r * SEQ + kt + c4];
            *(uint2*)&Vw[r][c4 >> 1] =
                make_uint2(h2pack(vv.x, vv.y), h2pack(vv.z, vv.w));
        }
        __syncthreads();

        // S = (Q/8) K^T : 8 n-octets of keys
        float s[8][4] = {};
#pragma unroll
        for (int kc = 0; kc < 4; kc++)
#pragma unroll
            for (int ni = 0; ni < 8; ni++) {
                unsigned b0 = Kw[ni * 8 + lq][kc * 8 + lr];
                unsigned b1 = Kw[ni * 8 + lq][kc * 8 + 4 + lr];
                mma_f16(s[ni], qf[kc][0], qf[kc][1], qf[kc][2], qf[kc][3], b0, b1);
            }

        // + mask (scale already folded into Q)
#pragma unroll
        for (int ni = 0; ni < 8; ni++) {
            float2 mv = *(const float2*)&maskb[kt + ni * 8 + 2 * lr];
            s[ni][0] += mv.x; s[ni][1] += mv.y;
            s[ni][2] += mv.x; s[ni][3] += mv.y;
        }

        // Online softmax: rows lq (frags 0,1) and lq+8 (frags 2,3);
        // 4-lane row groups -> xor 1,2 shuffles.
        float tm1 = -1e30f, tm2 = -1e30f;
#pragma unroll
        for (int ni = 0; ni < 8; ni++) {
            tm1 = fmaxf(tm1, fmaxf(s[ni][0], s[ni][1]));
            tm2 = fmaxf(tm2, fmaxf(s[ni][2], s[ni][3]));
        }
        tm1 = fmaxf(tm1, __shfl_xor_sync(0xffffffffu, tm1, 1));
        tm1 = fmaxf(tm1, __shfl_xor_sync(0xffffffffu, tm1, 2));
        tm2 = fmaxf(tm2, __shfl_xor_sync(0xffffffffu, tm2, 1));
        tm2 = fmaxf(tm2, __shfl_xor_sync(0xffffffffu, tm2, 2));
        float nm1 = fmaxf(m1, tm1), nm2 = fmaxf(m2, tm2);
        float corr1 = __expf(m1 - nm1), corr2 = __expf(m2 - nm2);
        m1 = nm1; m2 = nm2;
        float ts1 = 0.f, ts2 = 0.f;
#pragma unroll
        for (int ni = 0; ni < 8; ni++) {
            s[ni][0] = __expf(s[ni][0] - nm1); ts1 += s[ni][0];
            s[ni][1] = __expf(s[ni][1] - nm1); ts1 += s[ni][1];
            s[ni][2] = __expf(s[ni][2] - nm2); ts2 += s[ni][2];
            s[ni][3] = __expf(s[ni][3] - nm2); ts2 += s[ni][3];
        }
        ts1 += __shfl_xor_sync(0xffffffffu, ts1, 1);
        ts1 += __shfl_xor_sync(0xffffffffu, ts1, 2);
        ts2 += __shfl_xor_sync(0xffffffffu, ts2, 1);
        ts2 += __shfl_xor_sync(0xffffffffu, ts2, 2);
        l1 = l1 * corr1 + ts1;
        l2 = l2 * corr2 + ts2;
#pragma unroll
        for (int di = 0; di < 8; di++) {
            o[di][0] *= corr1; o[di][1] *= corr1;
            o[di][2] *= corr2; o[di][3] *= corr2;
        }

        // O += P @ V : S C-frags re-packed straight into fp16 A-frags.
        // A-frag(kc): a0={P[lq][kc16+2lr,+1]}=s[2kc][0,1]; a1=rows lq+8 ->
        // s[2kc][2,3]; a2,a3 = keys +8 -> s[2kc+1][..].
#pragma unroll
        for (int kc = 0; kc < 4; kc++) {
            unsigned pa0 = h2pack(s[2 * kc][0],     s[2 * kc][1]);
            unsigned pa1 = h2pack(s[2 * kc][2],     s[2 * kc][3]);
            unsigned pa2 = h2pack(s[2 * kc + 1][0], s[2 * kc + 1][1]);
            unsigned pa3 = h2pack(s[2 * kc + 1][2], s[2 * kc + 1][3]);
#pragma unroll
            for (int di = 0; di < 8; di++) {
                unsigned b0 = Vw[di * 8 + lq][kc * 8 + lr];
                unsigned b1 = Vw[di * 8 + lq][kc * 8 + 4 + lr];
                mma_f16(o[di], pa0, pa1, pa2, pa3, b0, b1);
            }
        }
    }

    // Normalize + write A (same [m][h*64+d] layout as g_Q)
    float inv1 = 1.0f / l1, inv2 = 1.0f / l2;
#pragma unroll
    for (int di = 0; di < 8; di++) {
        int col  = h * HEAD_DIM + di * 8 + 2 * lr;
        int row1 = m0 + q0 + lq;
        *(float2*)&g_A[(size_t)row1 * HIDDEN + col] =
            make_float2(o[di][0] * inv1, o[di][1] * inv1);
        *(float2*)&g_A[(size_t)(row1 + 8) * HIDDEN + col] =
            make_float2(o[di][2] * inv2, o[di][3] * inv2);
    }
}

// ---------------------------------------------------------------------------
extern "C" void kernel_launch(void* const* d_in, const int* in_sizes, int n_in,
                              void* d_out, int out_size)
{
    const float* x    = (const float*)d_in[0];
    const float* mask = (const float*)d_in[1];
    const float* Wq   = (const float*)d_in[2];
    const float* bq   = (const float*)d_in[3];
    const float* Wk   = (const float*)d_in[4];
    const float* bk   = (const float*)d_in[5];
    const float* Wv   = (const float*)d_in[6];
    const float* bv   = (const float*)d_in[7];
    const float* Wo   = (const float*)d_in[8];
    const float* bo   = (const float*)d_in[9];
    float* out = (float*)d_out;

    float *q, *k, *v, *a;
    cudaGetSymbolAddress((void**)&q, g_Q);
    cudaGetSymbolAddress((void**)&k, g_K);
    cudaGetSymbolAddress((void**)&v, g_V);
    cudaGetSymbolAddress((void**)&a, g_A);

    dim3 blk(256);
    // Q = x @ Wq + bq
    gemm_tf32<<<dim3(HIDDEN / 128, MTOT / 128), blk>>>(x, Wq, bq, q, MTOT, HIDDEN, HIDDEN, 0);
    // K = x @ Wk + bk
    gemm_tf32<<<dim3(KVSIZE / 128, MTOT / 128), blk>>>(x, Wk, bk, k, MTOT, KVSIZE, HIDDEN, 0);
    // V = x @ Wv + bv, stored transposed [(b*8+kvh)*64+d][seq]
    gemm_tf32<<<dim3(KVSIZE / 128, MTOT / 128), blk>>>(x, Wv, bv, v, MTOT, KVSIZE, HIDDEN, 1);
    // Fused fp16 flash attention
    flash_fp16<<<dim3(SEQ / 64, HEADS, BATCH), dim3(128)>>>(mask);
    // out = A @ Wo + bo
    gemm_tf32<<<dim3(HIDDEN / 128, MTOT / 128), blk>>>(a, Wo, bo, out, MTOT, HIDDEN, HIDDEN, 0);
}

// round 10
// speedup vs baseline: 4.4649x; 1.3034x over previous
#include <cuda_runtime.h>
#include <cuda_fp16.h>
#include <cstdint>

#define HIDDEN   2048
#define KVSIZE   512
#define HEAD_DIM 64
#define BATCH    2
#define SEQ      2048
#define MTOT     (BATCH * SEQ)

// Scratch (device globals: allocation inside kernel_launch is forbidden)
__device__ __half g_Qh[MTOT * HIDDEN];  // fp16, PRESCALED by 0.125, [m][h*64+d]
__device__ __half g_Kh[MTOT * KVSIZE];  // fp16, [m][kvh*64+d]
__device__ __half g_Vh[MTOT * KVSIZE];  // fp16, TRANSPOSED [(b*8+kvh)*64+d][seq]
__device__ float  g_A [MTOT * HIDDEN];  // attention output fp32, [m][h*64+d]

// ---------------------------------------------------------------------------
// helpers
// ---------------------------------------------------------------------------
__device__ __forceinline__ unsigned f2tf(float f) {
    unsigned u;
    asm("cvt.rna.tf32.f32 %0, %1;" : "=r"(u) : "f"(f));
    return u;
}
__device__ __forceinline__ unsigned h2pack(float lo, float hi) {
    unsigned r;
    asm("cvt.rn.f16x2.f32 %0, %1, %2;" : "=r"(r) : "f"(hi), "f"(lo));
    return r;
}
__device__ __forceinline__ unsigned sptr(const void* p) {
    return (unsigned)__cvta_generic_to_shared(p);
}
__device__ __forceinline__ void mma_tf32(float c[4],
                                         unsigned a0, unsigned a1, unsigned a2, unsigned a3,
                                         unsigned b0, unsigned b1) {
    asm("mma.sync.aligned.m16n8k8.row.col.f32.tf32.tf32.f32 "
        "{%0,%1,%2,%3}, {%4,%5,%6,%7}, {%8,%9}, {%0,%1,%2,%3};"
        : "+f"(c[0]), "+f"(c[1]), "+f"(c[2]), "+f"(c[3])
        : "r"(a0), "r"(a1), "r"(a2), "r"(a3), "r"(b0), "r"(b1));
}
__device__ __forceinline__ void mma_f16(float c[4],
                                        unsigned a0, unsigned a1, unsigned a2, unsigned a3,
                                        unsigned b0, unsigned b1) {
    asm("mma.sync.aligned.m16n8k16.row.col.f32.f16.f16.f32 "
        "{%0,%1,%2,%3}, {%4,%5,%6,%7}, {%8,%9}, {%0,%1,%2,%3};"
        : "+f"(c[0]), "+f"(c[1]), "+f"(c[2]), "+f"(c[3])
        : "r"(a0), "r"(a1), "r"(a2), "r"(a3), "r"(b0), "r"(b1));
}

// ---------------------------------------------------------------------------
// Pipelined tf32 GEMM: C = A@B + bias. 128x128x32 tile, 256 thr, 8 warps.
// cp.async 2-stage double buffer; fp32 in smem, cvt.rna.tf32 at frag load.
// Pitches 40 / 136 (≡8 mod 32) -> conflict-free fragment LDS.
// qkv != 0: fused QKV launch, grid.x = 24: [0,16) Q, [16,20) K, [20,24) V.
//   mode Q: g_Qh half, (acc+bias)*0.125
//   mode K: g_Kh half
//   mode V: g_Vh half, transposed [(b*8+kvh)*64+d][seq]
// qkv == 0: O projection, fp32 to Cout.
// ---------------------------------------------------------------------------
#define GA_P 40
#define GB_P 136
#define STG  (128 * GA_P + 32 * GB_P)   // 9472 words per stage

__global__ __launch_bounds__(256) void gemm_pipe(
    const float* __restrict__ A,
    const float* __restrict__ W0, const float* __restrict__ b0p,
    const float* __restrict__ W1, const float* __restrict__ b1p,
    const float* __restrict__ W2, const float* __restrict__ b2p,
    float* __restrict__ Cout, int qkv)
{
    extern __shared__ float sm[];

    const int tid  = threadIdx.x;
    const int lane = tid & 31;
    const int w    = tid >> 5;
    const int lq = lane >> 2, lr = lane & 3;
    const int wm = (w >> 2) * 64;
    const int wn = (w & 3) * 32;
    const int brow = blockIdx.y * 128;
    const int K = HIDDEN;

    const float* B; const float* bias; int N, bcol, mode;
    int bx = blockIdx.x;
    if (qkv) {
        if (bx < 16)      { B = W0; bias = b0p; N = HIDDEN; bcol = bx * 128;        mode = 1; }
        else if (bx < 20) { B = W1; bias = b1p; N = KVSIZE; bcol = (bx - 16) * 128; mode = 2; }
        else              { B = W2; bias = b2p; N = KVSIZE; bcol = (bx - 20) * 128; mode = 3; }
    } else                { B = W0; bias = b0p; N = HIDDEN; bcol = bx * 128;        mode = 0; }

    auto issue = [&](int st, int kt) {
        float* As = sm + st * STG;
        float* Bs = As + 128 * GA_P;
#pragma unroll
        for (int i = 0; i < 4; i++) {         // A tile 128x32 fp32
            int ch = tid + i * 256;
            int r = ch >> 3, c4 = (ch & 7) << 2;
            unsigned d = sptr(As + r * GA_P + c4);
            const float* s = A + (size_t)(brow + r) * K + kt + c4;
            asm volatile("cp.async.cg.shared.global [%0], [%1], 16;" :: "r"(d), "l"(s));
        }
#pragma unroll
        for (int i = 0; i < 4; i++) {         // B tile 32x128 fp32
            int ch = tid + i * 256;
            int r = ch >> 5, c4 = (ch & 31) << 2;
            unsigned d = sptr(Bs + r * GB_P + c4);
            const float* s = B + (size_t)(kt + r) * N + bcol + c4;
            asm volatile("cp.async.cg.shared.global [%0], [%1], 16;" :: "r"(d), "l"(s));
        }
        asm volatile("cp.async.commit_group;");
    };

    issue(0, 0);

    float c[4][4][4] = {};
    const int T = K / 32;
    for (int t = 0; t < T; t++) {
        asm volatile("cp.async.wait_group 0;");
        __syncthreads();                       // stage t visible; compute(t-1) done
        if (t + 1 < T) issue((t + 1) & 1, (t + 1) * 32);

        const float* Asf = sm + (t & 1) * STG;
        const float* Bsf = Asf + 128 * GA_P;
#pragma unroll
        for (int kk = 0; kk < 32; kk += 8) {
            unsigned a[4][4], bf[4][2];
#pragma unroll
            for (int mi = 0; mi < 4; mi++) {
                int r0 = wm + mi * 16 + lq;
                a[mi][0] = f2tf(Asf[r0 * GA_P + kk + lr]);
                a[mi][1] = f2tf(Asf[(r0 + 8) * GA_P + kk + lr]);
                a[mi][2] = f2tf(Asf[r0 * GA_P + kk + 4 + lr]);
                a[mi][3] = f2tf(Asf[(r0 + 8) * GA_P + kk + 4 + lr]);
            }
#pragma unroll
            for (int ni = 0; ni < 4; ni++) {
                int c0 = wn + ni * 8 + lq;
                bf[ni][0] = f2tf(Bsf[(kk + lr) * GB_P + c0]);
                bf[ni][1] = f2tf(Bsf[(kk + 4 + lr) * GB_P + c0]);
            }
#pragma unroll
            for (int mi = 0; mi < 4; mi++)
#pragma unroll
                for (int ni = 0; ni < 4; ni++)
                    mma_tf32(c[mi][ni], a[mi][0], a[mi][1], a[mi][2], a[mi][3],
                             bf[ni][0], bf[ni][1]);
        }
    }

    // Epilogue
#pragma unroll
    for (int mi = 0; mi < 4; mi++)
#pragma unroll
        for (int ni = 0; ni < 4; ni++) {
            int row = brow + wm + mi * 16 + lq;
            int col = bcol + wn + ni * 8 + 2 * lr;
            float v0 = c[mi][ni][0] + bias[col];
            float v1 = c[mi][ni][1] + bias[col + 1];
            float v2 = c[mi][ni][2] + bias[col];
            float v3 = c[mi][ni][3] + bias[col + 1];
            if (mode == 0) {
                *(float2*)&Cout[(size_t)row * N + col]       = make_float2(v0, v1);
                *(float2*)&Cout[(size_t)(row + 8) * N + col] = make_float2(v2, v3);
            } else if (mode == 1) {           // Q: prescale by 1/sqrt(64), fp16
                *(__half2*)&g_Qh[(size_t)row * HIDDEN + col] =
                    __floats2half2_rn(v0 * 0.125f, v1 * 0.125f);
                *(__half2*)&g_Qh[(size_t)(row + 8) * HIDDEN + col] =
                    __floats2half2_rn(v2 * 0.125f, v3 * 0.125f);
            } else if (mode == 2) {           // K: fp16
                *(__half2*)&g_Kh[(size_t)row * KVSIZE + col] = __floats2half2_rn(v0, v1);
                *(__half2*)&g_Kh[(size_t)(row + 8) * KVSIZE + col] = __floats2half2_rn(v2, v3);
            } else {                          // V: fp16, transposed scatter
                size_t base0 = ((size_t)((row >> 11) * 512) + col) * SEQ + (row & 2047);
                g_Vh[base0]       = __float2half(v0);
                g_Vh[base0 + SEQ] = __float2half(v1);
                int r8 = row + 8;
                size_t base1 = ((size_t)((r8 >> 11) * 512) + col) * SEQ + (r8 & 2047);
                g_Vh[base1]       = __float2half(v2);
                g_Vh[base1 + SEQ] = __float2half(v3);
            }
        }
}

// ---------------------------------------------------------------------------
// Flash attention, fp16 mma, cp.async double-buffered K/V, ONE barrier/tile.
// Grid (SEQ/64, 32, 2). Block 128 thr = 4 warps; warp w = q-rows [16w,16w+16).
// Smem word tiles pitch 36 (≡4 mod 32; frag pattern 4*lq+lr conflict-free):
//   Qw[64][36], Kw[2][64][36], Vw[2][64][36]  (half2 words)  = 46 KB.
// Fills are raw fp16 cp.async (conversion done in projection epilogues).
// P: S C-frags repacked directly into PV A-frags (no smem round-trip).
// ---------------------------------------------------------------------------
__global__ __launch_bounds__(128) void flash_cp(const float* __restrict__ mask)
{
    __shared__ unsigned Qw[64][36];
    __shared__ unsigned Kw[2][64][36];
    __shared__ unsigned Vw[2][64][36];

    const int tid  = threadIdx.x;
    const int lane = tid & 31;
    const int w    = tid >> 5;
    const int lq = lane >> 2, lr = lane & 3;
    const int h   = blockIdx.y;
    const int b   = blockIdx.z;
    const int kvh = h >> 2;
    const int m0  = b * SEQ + blockIdx.x * 64;
    const int q0  = w * 16;
    const float* maskb = mask + b * SEQ;
    const __half* Vg = g_Vh + (size_t)(b * 8 + kvh) * 64 * SEQ;   // [d][seq]

    auto issue_kv = [&](int buf, int kt) {
#pragma unroll
        for (int i = 0; i < 4; i++) {
            int ch = i * 128 + tid;
            int r = ch >> 3, c8 = (ch & 7) << 3;      // 64 rows x 8 chunks(16B)
            unsigned dk = sptr(&Kw[buf][r][c8 >> 1]);
            const __half* sk = g_Kh + (size_t)(b * SEQ + kt + r) * KVSIZE + kvh * 64 + c8;
            asm volatile("cp.async.ca.shared.global [%0], [%1], 16;" :: "r"(dk), "l"(sk));
            unsigned dv = sptr(&Vw[buf][r][c8 >> 1]);
            const __half* sv = Vg + (size_t)r * SEQ + kt + c8;
            asm volatile("cp.async.ca.shared.global [%0], [%1], 16;" :: "r"(dv), "l"(sv));
        }
        asm volatile("cp.async.commit_group;");
    };

    // Q fill (joins first commit group) + K/V tile 0
#pragma unroll
    for (int i = 0; i < 4; i++) {
        int ch = i * 128 + tid;
        int r = ch >> 3, c8 = (ch & 7) << 3;
        unsigned d = sptr(&Qw[r][c8 >> 1]);
        const __half* s = g_Qh + (size_t)(m0 + r) * HIDDEN + h * HEAD_DIM + c8;
        asm volatile("cp.async.ca.shared.global [%0], [%1], 16;" :: "r"(d), "l"(s));
    }
    issue_kv(0, 0);
    asm volatile("cp.async.wait_group 0;");
    __syncthreads();

    // Q A-fragments (already prescaled)
    unsigned qf[4][4];
#pragma unroll
    for (int kc = 0; kc < 4; kc++) {
        qf[kc][0] = Qw[q0 + lq][kc * 8 + lr];
        qf[kc][1] = Qw[q0 + 8 + lq][kc * 8 + lr];
        qf[kc][2] = Qw[q0 + lq][kc * 8 + 4 + lr];
        qf[kc][3] = Qw[q0 + 8 + lq][kc * 8 + 4 + lr];
    }

    float m1 = -1e30f, m2 = -1e30f, l1 = 0.f, l2 = 0.f;
    float o[8][4] = {};

    for (int t = 0; t < SEQ / 64; t++) {
        if (t) {
            asm volatile("cp.async.wait_group 0;");
            __syncthreads();                  // tile t ready; compute(t-1) done
        }
        if (t + 1 < SEQ / 64) issue_kv((t + 1) & 1, (t + 1) * 64);

        const unsigned (*Kb)[36] = Kw[t & 1];
        const unsigned (*Vb)[36] = Vw[t & 1];
        const int kt = t * 64;

        // S = (Q/8) K^T
        float s[8][4] = {};
#pragma unroll
        for (int kc = 0; kc < 4; kc++)
#pragma unroll
            for (int ni = 0; ni < 8; ni++) {
                unsigned b0 = Kb[ni * 8 + lq][kc * 8 + lr];
                unsigned b1 = Kb[ni * 8 + lq][kc * 8 + 4 + lr];
                mma_f16(s[ni], qf[kc][0], qf[kc][1], qf[kc][2], qf[kc][3], b0, b1);
            }

        // + mask
#pragma unroll
        for (int ni = 0; ni < 8; ni++) {
            float2 mv = *(const float2*)&maskb[kt + ni * 8 + 2 * lr];
            s[ni][0] += mv.x; s[ni][1] += mv.y;
            s[ni][2] += mv.x; s[ni][3] += mv.y;
        }

        // Online softmax (rows lq / lq+8; 4-lane groups -> xor 1,2)
        float tm1 = -1e30f, tm2 = -1e30f;
#pragma unroll
        for (int ni = 0; ni < 8; ni++) {
            tm1 = fmaxf(tm1, fmaxf(s[ni][0], s[ni][1]));
            tm2 = fmaxf(tm2, fmaxf(s[ni][2], s[ni][3]));
        }
        tm1 = fmaxf(tm1, __shfl_xor_sync(0xffffffffu, tm1, 1));
        tm1 = fmaxf(tm1, __shfl_xor_sync(0xffffffffu, tm1, 2));
        tm2 = fmaxf(tm2, __shfl_xor_sync(0xffffffffu, tm2, 1));
        tm2 = fmaxf(tm2, __shfl_xor_sync(0xffffffffu, tm2, 2));
        float nm1 = fmaxf(m1, tm1), nm2 = fmaxf(m2, tm2);
        float corr1 = __expf(m1 - nm1), corr2 = __expf(m2 - nm2);
        m1 = nm1; m2 = nm2;
        float ts1 = 0.f, ts2 = 0.f;
#pragma unroll
        for (int ni = 0; ni < 8; ni++) {
            s[ni][0] = __expf(s[ni][0] - nm1); ts1 += s[ni][0];
            s[ni][1] = __expf(s[ni][1] - nm1); ts1 += s[ni][1];
            s[ni][2] = __expf(s[ni][2] - nm2); ts2 += s[ni][2];
            s[ni][3] = __expf(s[ni][3] - nm2); ts2 += s[ni][3];
        }
        ts1 += __shfl_xor_sync(0xffffffffu, ts1, 1);
        ts1 += __shfl_xor_sync(0xffffffffu, ts1, 2);
        ts2 += __shfl_xor_sync(0xffffffffu, ts2, 1);
        ts2 += __shfl_xor_sync(0xffffffffu, ts2, 2);
        l1 = l1 * corr1 + ts1;
        l2 = l2 * corr2 + ts2;
#pragma unroll
        for (int di = 0; di < 8; di++) {
            o[di][0] *= corr1; o[di][1] *= corr1;
            o[di][2] *= corr2; o[di][3] *= corr2;
        }

        // O += P @ V (C-frag -> A-frag repack, FA2 identity)
#pragma unroll
        for (int kc = 0; kc < 4; kc++) {
            unsigned pa0 = h2pack(s[2 * kc][0],     s[2 * kc][1]);
            unsigned pa1 = h2pack(s[2 * kc][2],     s[2 * kc][3]);
            unsigned pa2 = h2pack(s[2 * kc + 1][0], s[2 * kc + 1][1]);
            unsigned pa3 = h2pack(s[2 * kc + 1][2], s[2 * kc + 1][3]);
#pragma unroll
            for (int di = 0; di < 8; di++) {
                unsigned b0 = Vb[di * 8 + lq][kc * 8 + lr];
                unsigned b1 = Vb[di * 8 + lq][kc * 8 + 4 + lr];
                mma_f16(o[di], pa0, pa1, pa2, pa3, b0, b1);
            }
        }
    }

    // Normalize + write A
    float inv1 = 1.0f / l1, inv2 = 1.0f / l2;
#pragma unroll
    for (int di = 0; di < 8; di++) {
        int col  = h * HEAD_DIM + di * 8 + 2 * lr;
        int row1 = m0 + q0 + lq;
        *(float2*)&g_A[(size_t)row1 * HIDDEN + col] =
            make_float2(o[di][0] * inv1, o[di][1] * inv1);
        *(float2*)&g_A[(size_t)(row1 + 8) * HIDDEN + col] =
            make_float2(o[di][2] * inv2, o[di][3] * inv2);
    }
}

// ---------------------------------------------------------------------------
extern "C" void kernel_launch(void* const* d_in, const int* in_sizes, int n_in,
                              void* d_out, int out_size)
{
    const float* x    = (const float*)d_in[0];
    const float* mask = (const float*)d_in[1];
    const float* Wq   = (const float*)d_in[2];
    const float* bq   = (const float*)d_in[3];
    const float* Wk   = (const float*)d_in[4];
    const float* bk   = (const float*)d_in[5];
    const float* Wv   = (const float*)d_in[6];
    const float* bv   = (const float*)d_in[7];
    const float* Wo   = (const float*)d_in[8];
    const float* bo   = (const float*)d_in[9];
    float* out = (float*)d_out;

    float* a;
    cudaGetSymbolAddress((void**)&a, g_A);

    const int GSMEM = 2 * STG * (int)sizeof(float);   // 75776 B
    cudaFuncSetAttribute((const void*)gemm_pipe,
                         cudaFuncAttributeMaxDynamicSharedMemorySize, GSMEM);

    // Fused QKV projections (grid.x: 16 Q-col-blocks + 4 K + 4 V)
    gemm_pipe<<<dim3(24, MTOT / 128), 256, GSMEM>>>(x, Wq, bq, Wk, bk, Wv, bv, nullptr, 1);
    // Fused fp16 flash attention
    flash_cp<<<dim3(SEQ / 64, 32, BATCH), dim3(128)>>>(mask);
    // out = A @ Wo + bo
    gemm_pipe<<<dim3(16, MTOT / 128), 256, GSMEM>>>(a, Wo, bo, nullptr, nullptr,
                                                    nullptr, nullptr, out, 0);
}

// round 13
// speedup vs baseline: 4.5724x; 1.0241x over previous
#include <cuda_runtime.h>
#include <cuda_fp16.h>
#include <cstdint>

#define HIDDEN   2048
#define KVSIZE   512
#define HEAD_DIM 64
#define BATCH    2
#define SEQ      2048
#define MTOT     (BATCH * SEQ)

// Scratch (device globals: allocation inside kernel_launch is forbidden)
__device__ __half g_xh [MTOT * HIDDEN];    // x in fp16
__device__ __half g_Wqh[HIDDEN * HIDDEN];
__device__ __half g_Wkh[HIDDEN * KVSIZE];
__device__ __half g_Wvh[HIDDEN * KVSIZE];
__device__ __half g_Woh[HIDDEN * HIDDEN];
__device__ __half g_Qh [MTOT * HIDDEN];    // PRESCALED by 0.125, [m][h*64+d]
__device__ __half g_Kh [MTOT * KVSIZE];    // [m][kvh*64+d]
__device__ __half g_Vh [MTOT * KVSIZE];    // TRANSPOSED [(b*8+kvh)*64+d][seq]
__device__ __half g_Ah [MTOT * HIDDEN];    // attention output fp16, [m][h*64+d]

// ---------------------------------------------------------------------------
// helpers
// ---------------------------------------------------------------------------
__device__ __forceinline__ unsigned h2pack(float lo, float hi) {
    unsigned r;
    asm("cvt.rn.f16x2.f32 %0, %1, %2;" : "=r"(r) : "f"(hi), "f"(lo));
    return r;
}
__device__ __forceinline__ unsigned sptr(const void* p) {
    return (unsigned)__cvta_generic_to_shared(p);
}
__device__ __forceinline__ void mma_f16(float c[4],
                                        unsigned a0, unsigned a1, unsigned a2, unsigned a3,
                                        unsigned b0, unsigned b1) {
    asm("mma.sync.aligned.m16n8k16.row.col.f32.f16.f16.f32 "
        "{%0,%1,%2,%3}, {%4,%5,%6,%7}, {%8,%9}, {%0,%1,%2,%3};"
        : "+f"(c[0]), "+f"(c[1]), "+f"(c[2]), "+f"(c[3])
        : "r"(a0), "r"(a1), "r"(a2), "r"(a3), "r"(b0), "r"(b1));
}
__device__ __forceinline__ void ldsm4(unsigned& r0, unsigned& r1, unsigned& r2, unsigned& r3,
                                      unsigned addr) {
    asm volatile("ldmatrix.sync.aligned.m8n8.x4.shared.b16 {%0,%1,%2,%3}, [%4];"
                 : "=r"(r0), "=r"(r1), "=r"(r2), "=r"(r3) : "r"(addr));
}
__device__ __forceinline__ void ldsm4t(unsigned& r0, unsigned& r1, unsigned& r2, unsigned& r3,
                                       unsigned addr) {
    asm volatile("ldmatrix.sync.aligned.m8n8.x4.trans.shared.b16 {%0,%1,%2,%3}, [%4];"
                 : "=r"(r0), "=r"(r1), "=r"(r2), "=r"(r3) : "r"(addr));
}

// ---------------------------------------------------------------------------
// fp32 -> fp16 bulk convert (n multiple of 4)
// ---------------------------------------------------------------------------
__global__ __launch_bounds__(256) void f2h(const float* __restrict__ s,
                                           __half* __restrict__ d, int n) {
    int i = (blockIdx.x * 256 + threadIdx.x) * 4;
    if (i < n) {
        float4 v = *(const float4*)(s + i);
        *(__half2*)(d + i)     = __floats2half2_rn(v.x, v.y);
        *(__half2*)(d + i + 2) = __floats2half2_rn(v.z, v.w);
    }
}

// ---------------------------------------------------------------------------
// fp16 GEMM: C = A@B + bias. 128x128x32 tile, 256 thr (8 warps), warp 64x32.
// cp.async 3-stage pipeline, ldmatrix fragment loads, m16n8k16 mma.
// A pitch 40 halves (80B): ldmatrix phase banks {0,20,8,28,...} conflict-free.
// B pitch 136 halves (272B): banks {0,4,...,28} conflict-free (.trans).
// qkv != 0: fused QKV, grid.x = 24: [0,16) Q, [16,20) K, [20,24) V.
// qkv == 0: O projection, fp32 out.
// ---------------------------------------------------------------------------
#define PA 40
#define PB 136
#define HSTG (128 * PA + 32 * PB)   // 9472 halves / stage (18944 B)

__global__ __launch_bounds__(256) void gemm_h(
    const __half* __restrict__ A,
    const __half* __restrict__ W0, const float* __restrict__ b0p,
    const __half* __restrict__ W1, const float* __restrict__ b1p,
    const __half* __restrict__ W2, const float* __restrict__ b2p,
    float* __restrict__ Cout, int qkv)
{
    extern __shared__ __half sm[];

    const int tid  = threadIdx.x;
    const int lane = tid & 31;
    const int w    = tid >> 5;
    const int lq = lane >> 2, lr = lane & 3;
    const int wm = (w >> 2) * 64;
    const int wn = (w & 3) * 32;
    const int brow = blockIdx.y * 128;
    const int K = HIDDEN;

    const __half* B; const float* bias; int N, bcol, mode;
    int bx = blockIdx.x;
    if (qkv) {
        if (bx < 16)      { B = W0; bias = b0p; N = HIDDEN; bcol = bx * 128;        mode = 1; }
        else if (bx < 20) { B = W1; bias = b1p; N = KVSIZE; bcol = (bx - 16) * 128; mode = 2; }
        else              { B = W2; bias = b2p; N = KVSIZE; bcol = (bx - 20) * 128; mode = 3; }
    } else                { B = W0; bias = b0p; N = HIDDEN; bcol = bx * 128;        mode = 0; }

    auto issue = [&](int st, int kt) {
        __half* As = sm + st * HSTG;
        __half* Bs = As + 128 * PA;
#pragma unroll
        for (int i = 0; i < 2; i++) {          // A: 128 x 32 halves, 512 x 16B
            int ch = tid + i * 256;
            int r = ch >> 2, c8 = (ch & 3) << 3;
            unsigned d = sptr(As + r * PA + c8);
            const __half* s = A + (size_t)(brow + r) * K + kt + c8;
            asm volatile("cp.async.ca.shared.global [%0], [%1], 16;" :: "r"(d), "l"(s));
        }
#pragma unroll
        for (int i = 0; i < 2; i++) {          // B: 32 x 128 halves, 512 x 16B
            int ch = tid + i * 256;
            int r = ch >> 4, c8 = (ch & 15) << 3;
            unsigned d = sptr(Bs + r * PB + c8);
            const __half* s = B + (size_t)(kt + r) * N + bcol + c8;
            asm volatile("cp.async.ca.shared.global [%0], [%1], 16;" :: "r"(d), "l"(s));
        }
        asm volatile("cp.async.commit_group;");
    };

    issue(0, 0);
    issue(1, 32);

    float c[4][4][4] = {};
    const int T = K / 32;
    for (int t = 0; t < T; t++) {
        asm volatile("cp.async.wait_group 1;");   // stage t landed
        __syncthreads();                          // compute(t-1) fully done
        if (t + 2 < T) issue((t + 2) % 3, (t + 2) * 32);

        const __half* Asf = sm + (t % 3) * HSTG;
        const __half* Bsf = Asf + 128 * PA;
#pragma unroll
        for (int kk = 0; kk < 32; kk += 16) {
            unsigned a[4][4], bf[4][2];
#pragma unroll
            for (int mi = 0; mi < 4; mi++) {
                unsigned ad = sptr(Asf + (size_t)(wm + mi * 16 + (lane & 15)) * PA
                                   + kk + ((lane >> 4) << 3));
                ldsm4(a[mi][0], a[mi][1], a[mi][2], a[mi][3], ad);
            }
#pragma unroll
            for (int np = 0; np < 2; np++) {
                int m = lane >> 3;
                int krow = kk + (m & 1) * 8 + (lane & 7);
                int ncol = wn + np * 16 + (m >> 1) * 8;
                unsigned bd = sptr(Bsf + (size_t)krow * PB + ncol);
                ldsm4t(bf[np * 2][0], bf[np * 2][1], bf[np * 2 + 1][0], bf[np * 2 + 1][1], bd);
            }
#pragma unroll
            for (int mi = 0; mi < 4; mi++)
#pragma unroll
                for (int ni = 0; ni < 4; ni++)
                    mma_f16(c[mi][ni], a[mi][0], a[mi][1], a[mi][2], a[mi][3],
                            bf[ni][0], bf[ni][1]);
        }
    }

    // Epilogue (fp32 accum + bias)
#pragma unroll
    for (int mi = 0; mi < 4; mi++)
#pragma unroll
        for (int ni = 0; ni < 4; ni++) {
            int row = brow + wm + mi * 16 + lq;
            int col = bcol + wn + ni * 8 + 2 * lr;
            float v0 = c[mi][ni][0] + bias[col];
            float v1 = c[mi][ni][1] + bias[col + 1];
            float v2 = c[mi][ni][2] + bias[col];
            float v3 = c[mi][ni][3] + bias[col + 1];
            if (mode == 0) {
                *(float2*)&Cout[(size_t)row * N + col]       = make_float2(v0, v1);
                *(float2*)&Cout[(size_t)(row + 8) * N + col] = make_float2(v2, v3);
            } else if (mode == 1) {            // Q: prescale 1/8, fp16
                *(__half2*)&g_Qh[(size_t)row * HIDDEN + col] =
                    __floats2half2_rn(v0 * 0.125f, v1 * 0.125f);
                *(__half2*)&g_Qh[(size_t)(row + 8) * HIDDEN + col] =
                    __floats2half2_rn(v2 * 0.125f, v3 * 0.125f);
            } else if (mode == 2) {            // K: fp16
                *(__half2*)&g_Kh[(size_t)row * KVSIZE + col] = __floats2half2_rn(v0, v1);
                *(__half2*)&g_Kh[(size_t)(row + 8) * KVSIZE + col] = __floats2half2_rn(v2, v3);
            } else {                           // V: fp16, transposed scatter
                size_t base0 = ((size_t)((row >> 11) * 512) + col) * SEQ + (row & 2047);
                g_Vh[base0]       = __float2half(v0);
                g_Vh[base0 + SEQ] = __float2half(v1);
                int r8 = row + 8;
                size_t base1 = ((size_t)((r8 >> 11) * 512) + col) * SEQ + (r8 & 2047);
                g_Vh[base1]       = __float2half(v2);
                g_Vh[base1 + SEQ] = __float2half(v3);
            }
        }
}

// ---------------------------------------------------------------------------
// Flash attention, fp16 mma, cp.async double-buffered K/V, one barrier/tile.
// Grid (SEQ/64, 32, 2). Block 128 thr = 4 warps; warp w = q-rows [16w,16w+16).
// Smem word tiles pitch 36 (≡4 mod 32; frag pattern 4*lq+lr conflict-free).
// Output written directly as fp16 to g_Ah.
// ---------------------------------------------------------------------------
__global__ __launch_bounds__(128) void flash_cp(const float* __restrict__ mask)
{
    __shared__ unsigned Qw[64][36];
    __shared__ unsigned Kw[2][64][36];
    __shared__ unsigned Vw[2][64][36];

    const int tid  = threadIdx.x;
    const int lane = tid & 31;
    const int w    = tid >> 5;
    const int lq = lane >> 2, lr = lane & 3;
    const int h   = blockIdx.y;
    const int b   = blockIdx.z;
    const int kvh = h >> 2;
    const int m0  = b * SEQ + blockIdx.x * 64;
    const int q0  = w * 16;
    const float* maskb = mask + b * SEQ;
    const __half* Vg = g_Vh + (size_t)(b * 8 + kvh) * 64 * SEQ;   // [d][seq]

    auto issue_kv = [&](int buf, int kt) {
#pragma unroll
        for (int i = 0; i < 4; i++) {
            int ch = i * 128 + tid;
            int r = ch >> 3, c8 = (ch & 7) << 3;
            unsigned dk = sptr(&Kw[buf][r][c8 >> 1]);
            const __half* sk = g_Kh + (size_t)(b * SEQ + kt + r) * KVSIZE + kvh * 64 + c8;
            asm volatile("cp.async.ca.shared.global [%0], [%1], 16;" :: "r"(dk), "l"(sk));
            unsigned dv = sptr(&Vw[buf][r][c8 >> 1]);
            const __half* sv = Vg + (size_t)r * SEQ + kt + c8;
            asm volatile("cp.async.ca.shared.global [%0], [%1], 16;" :: "r"(dv), "l"(sv));
        }
        asm volatile("cp.async.commit_group;");
    };

#pragma unroll
    for (int i = 0; i < 4; i++) {
        int ch = i * 128 + tid;
        int r = ch >> 3, c8 = (ch & 7) << 3;
        unsigned d = sptr(&Qw[r][c8 >> 1]);
        const __half* s = g_Qh + (size_t)(m0 + r) * HIDDEN + h * HEAD_DIM + c8;
        asm volatile("cp.async.ca.shared.global [%0], [%1], 16;" :: "r"(d), "l"(s));
    }
    issue_kv(0, 0);
    asm volatile("cp.async.wait_group 0;");
    __syncthreads();

    unsigned qf[4][4];
#pragma unroll
    for (int kc = 0; kc < 4; kc++) {
        qf[kc][0] = Qw[q0 + lq][kc * 8 + lr];
        qf[kc][1] = Qw[q0 + 8 + lq][kc * 8 + lr];
        qf[kc][2] = Qw[q0 + lq][kc * 8 + 4 + lr];
        qf[kc][3] = Qw[q0 + 8 + lq][kc * 8 + 4 + lr];
    }

    float m1 = -1e30f, m2 = -1e30f, l1 = 0.f, l2 = 0.f;
    float o[8][4] = {};

    for (int t = 0; t < SEQ / 64; t++) {
        if (t) {
            asm volatile("cp.async.wait_group 0;");
            __syncthreads();
        }
        if (t + 1 < SEQ / 64) issue_kv((t + 1) & 1, (t + 1) * 64);

        const unsigned (*Kb)[36] = Kw[t & 1];
        const unsigned (*Vb)[36] = Vw[t & 1];
        const int kt = t * 64;

        float s[8][4] = {};
#pragma unroll
        for (int kc = 0; kc < 4; kc++)
#pragma unroll
            for (int ni = 0; ni < 8; ni++) {
                unsigned b0 = Kb[ni * 8 + lq][kc * 8 + lr];
                unsigned b1 = Kb[ni * 8 + lq][kc * 8 + 4 + lr];
                mma_f16(s[ni], qf[kc][0], qf[kc][1], qf[kc][2], qf[kc][3], b0, b1);
            }

#pragma unroll
        for (int ni = 0; ni < 8; ni++) {
            float2 mv = *(const float2*)&maskb[kt + ni * 8 + 2 * lr];
            s[ni][0] += mv.x; s[ni][1] += mv.y;
            s[ni][2] += mv.x; s[ni][3] += mv.y;
        }

        float tm1 = -1e30f, tm2 = -1e30f;
#pragma unroll
        for (int ni = 0; ni < 8; ni++) {
            tm1 = fmaxf(tm1, fmaxf(s[ni][0], s[ni][1]));
            tm2 = fmaxf(tm2, fmaxf(s[ni][2], s[ni][3]));
        }
        tm1 = fmaxf(tm1, __shfl_xor_sync(0xffffffffu, tm1, 1));
        tm1 = fmaxf(tm1, __shfl_xor_sync(0xffffffffu, tm1, 2));
        tm2 = fmaxf(tm2, __shfl_xor_sync(0xffffffffu, tm2, 1));
        tm2 = fmaxf(tm2, __shfl_xor_sync(0xffffffffu, tm2, 2));
        float nm1 = fmaxf(m1, tm1), nm2 = fmaxf(m2, tm2);
        float corr1 = __expf(m1 - nm1), corr2 = __expf(m2 - nm2);
        m1 = nm1; m2 = nm2;
        float ts1 = 0.f, ts2 = 0.f;
#pragma unroll
        for (int ni = 0; ni < 8; ni++) {
            s[ni][0] = __expf(s[ni][0] - nm1); ts1 += s[ni][0];
            s[ni][1] = __expf(s[ni][1] - nm1); ts1 += s[ni][1];
            s[ni][2] = __expf(s[ni][2] - nm2); ts2 += s[ni][2];
            s[ni][3] = __expf(s[ni][3] - nm2); ts2 += s[ni][3];
        }
        ts1 += __shfl_xor_sync(0xffffffffu, ts1, 1);
        ts1 += __shfl_xor_sync(0xffffffffu, ts1, 2);
        ts2 += __shfl_xor_sync(0xffffffffu, ts2, 1);
        ts2 += __shfl_xor_sync(0xffffffffu, ts2, 2);
        l1 = l1 * corr1 + ts1;
        l2 = l2 * corr2 + ts2;
#pragma unroll
        for (int di = 0; di < 8; di++) {
            o[di][0] *= corr1; o[di][1] *= corr1;
            o[di][2] *= corr2; o[di][3] *= corr2;
        }

#pragma unroll
        for (int kc = 0; kc < 4; kc++) {
            unsigned pa0 = h2pack(s[2 * kc][0],     s[2 * kc][1]);
            unsigned pa1 = h2pack(s[2 * kc][2],     s[2 * kc][3]);
            unsigned pa2 = h2pack(s[2 * kc + 1][0], s[2 * kc + 1][1]);
            unsigned pa3 = h2pack(s[2 * kc + 1][2], s[2 * kc + 1][3]);
#pragma unroll
            for (int di = 0; di < 8; di++) {
                unsigned b0 = Vb[di * 8 + lq][kc * 8 + lr];
                unsigned b1 = Vb[di * 8 + lq][kc * 8 + 4 + lr];
                mma_f16(o[di], pa0, pa1, pa2, pa3, b0, b1);
            }
        }
    }

    // Normalize + write fp16 A
    float inv1 = 1.0f / l1, inv2 = 1.0f / l2;
#pragma unroll
    for (int di = 0; di < 8; di++) {
        int col  = h * HEAD_DIM + di * 8 + 2 * lr;
        int row1 = m0 + q0 + lq;
        *(__half2*)&g_Ah[(size_t)row1 * HIDDEN + col] =
            __floats2half2_rn(o[di][0] * inv1, o[di][1] * inv1);
        *(__half2*)&g_Ah[(size_t)(row1 + 8) * HIDDEN + col] =
            __floats2half2_rn(o[di][2] * inv2, o[di][3] * inv2);
    }
}

// ---------------------------------------------------------------------------
extern "C" void kernel_launch(void* const* d_in, const int* in_sizes, int n_in,
                              void* d_out, int out_size)
{
    const float* x    = (const float*)d_in[0];
    const float* mask = (const float*)d_in[1];
    const float* Wq   = (const float*)d_in[2];
    const float* bq   = (const float*)d_in[3];
    const float* Wk   = (const float*)d_in[4];
    const float* bk   = (const float*)d_in[5];
    const float* Wv   = (const float*)d_in[6];
    const float* bv   = (const float*)d_in[7];
    const float* Wo   = (const float*)d_in[8];
    const float* bo   = (const float*)d_in[9];
    float* out = (float*)d_out;

    __half *xh, *wqh, *wkh, *wvh, *woh, *ah;
    cudaGetSymbolAddress((void**)&xh,  g_xh);
    cudaGetSymbolAddress((void**)&wqh, g_Wqh);
    cudaGetSymbolAddress((void**)&wkh, g_Wkh);
    cudaGetSymbolAddress((void**)&wvh, g_Wvh);
    cudaGetSymbolAddress((void**)&woh, g_Woh);
    cudaGetSymbolAddress((void**)&ah,  g_Ah);

    const int GSMEM = 3 * HSTG * (int)sizeof(__half);   // 56832 B
    cudaFuncSetAttribute((const void*)gemm_h,
                         cudaFuncAttributeMaxDynamicSharedMemorySize, GSMEM);

    // fp32 -> fp16 conversions
    f2h<<<(MTOT * HIDDEN / 4 + 255) / 256, 256>>>(x,  xh,  MTOT * HIDDEN);
    f2h<<<(HIDDEN * HIDDEN / 4 + 255) / 256, 256>>>(Wq, wqh, HIDDEN * HIDDEN);
    f2h<<<(HIDDEN * KVSIZE / 4 + 255) / 256, 256>>>(Wk, wkh, HIDDEN * KVSIZE);
    f2h<<<(HIDDEN * KVSIZE / 4 + 255) / 256, 256>>>(Wv, wvh, HIDDEN * KVSIZE);
    f2h<<<(HIDDEN * HIDDEN / 4 + 255) / 256, 256>>>(Wo, woh, HIDDEN * HIDDEN);

    // Fused QKV projections (fp16 tensor cores)
    gemm_h<<<dim3(24, MTOT / 128), 256, GSMEM>>>(xh, wqh, bq, wkh, bk, wvh, bv, nullptr, 1);
    // Fused fp16 flash attention
    flash_cp<<<dim3(SEQ / 64, 32, BATCH), dim3(128)>>>(mask);
    // out = A @ Wo + bo
    gemm_h<<<dim3(16, MTOT / 128), 256, GSMEM>>>(ah, woh, bo, nullptr, nullptr,
                                                 nullptr, nullptr, out, 0);
}

// round 15
// speedup vs baseline: 7.0034x; 1.5317x over previous
#include <cuda_runtime.h>
#include <cuda_fp16.h>
#include <cstdint>

#define HIDDEN   2048
#define KVSIZE   512
#define HEAD_DIM 64
#define BATCH    2
#define SEQ      2048
#define MTOT     (BATCH * SEQ)

// Scratch (device globals: allocation inside kernel_launch is forbidden)
__device__ __half g_xh [MTOT * HIDDEN];    // x fp16, [m][k]
__device__ __half g_Wqh[HIDDEN * HIDDEN];  // weights fp16, [k][n]
__device__ __half g_Wkh[HIDDEN * KVSIZE];
__device__ __half g_Wvh[HIDDEN * KVSIZE];
__device__ __half g_Woh[HIDDEN * HIDDEN];
__device__ __half g_Qh [MTOT * HIDDEN];    // PRESCALED by 0.125, [m][h*64+d]
__device__ __half g_Kh [MTOT * KVSIZE];    // [m][kvh*64+d]
__device__ __half g_Vh [MTOT * KVSIZE];    // TRANSPOSED [(b*8+kvh)*64+d][seq]
__device__ __half g_Ah [MTOT * HIDDEN];    // attention out fp16, [m][h*64+d]

// ---------------------------------------------------------------------------
// helpers
// ---------------------------------------------------------------------------
__device__ __forceinline__ unsigned h2pack(float lo, float hi) {
    unsigned r;
    asm("cvt.rn.f16x2.f32 %0, %1, %2;" : "=r"(r) : "f"(hi), "f"(lo));
    return r;
}
__device__ __forceinline__ unsigned sptr(const void* p) {
    return (unsigned)__cvta_generic_to_shared(p);
}
__device__ __forceinline__ void mma_f16(float c[4],
                                        unsigned a0, unsigned a1, unsigned a2, unsigned a3,
                                        unsigned b0, unsigned b1) {
    asm("mma.sync.aligned.m16n8k16.row.col.f32.f16.f16.f32 "
        "{%0,%1,%2,%3}, {%4,%5,%6,%7}, {%8,%9}, {%0,%1,%2,%3};"
        : "+f"(c[0]), "+f"(c[1]), "+f"(c[2]), "+f"(c[3])
        : "r"(a0), "r"(a1), "r"(a2), "r"(a3), "r"(b0), "r"(b1));
}
__device__ __forceinline__ void ldsm4(unsigned& r0, unsigned& r1, unsigned& r2, unsigned& r3,
                                      unsigned addr) {
    asm volatile("ldmatrix.sync.aligned.m8n8.x4.shared.b16 {%0,%1,%2,%3}, [%4];"
                 : "=r"(r0), "=r"(r1), "=r"(r2), "=r"(r3) : "r"(addr));
}
__device__ __forceinline__ void ldsm4t(unsigned& r0, unsigned& r1, unsigned& r2, unsigned& r3,
                                       unsigned addr) {
    asm volatile("ldmatrix.sync.aligned.m8n8.x4.trans.shared.b16 {%0,%1,%2,%3}, [%4];"
                 : "=r"(r0), "=r"(r1), "=r"(r2), "=r"(r3) : "r"(addr));
}

// ---------------------------------------------------------------------------
// fp32 -> fp16 bulk convert
// ---------------------------------------------------------------------------
__global__ __launch_bounds__(256) void f2h(const float* __restrict__ s,
                                           __half* __restrict__ d, int n) {
    int i = (blockIdx.x * 256 + threadIdx.x) * 4;
    if (i < n) {
        float4 v = *(const float4*)(s + i);
        *(__half2*)(d + i)     = __floats2half2_rn(v.x, v.y);
        *(__half2*)(d + i + 2) = __floats2half2_rn(v.z, v.w);
    }
}

// ---------------------------------------------------------------------------
// fp16 GEMM: C = A@B + bias. 128x64x32 block tile, 128 thr (4 warps),
// warp tile 64x32 (warps: 2 in M x 2 in N). cp.async 3-stage, ldmatrix,
// m16n8k16 mma. Per-warp mainloop identical to the verified 256-thr version.
// A pitch 40 halves, B pitch 72 halves: ldmatrix phase banks {0,4,...,28}
// (both pitches ≡8 mod 32) -> conflict-free.
// qkv != 0: fused QKV, grid.x = 48: [0,32) Q, [32,40) K, [40,48) V.
// qkv == 0: O projection, fp32 out (N = HIDDEN, 32 col tiles).
// ---------------------------------------------------------------------------
#define PA 40
#define PB 72
#define HSTG (128 * PA + 32 * PB)   // 7424 halves / stage (14848 B)

__global__ __launch_bounds__(128) void gemm_h(
    const __half* __restrict__ A,
    const __half* __restrict__ W0, const float* __restrict__ b0p,
    const __half* __restrict__ W1, const float* __restrict__ b1p,
    const __half* __restrict__ W2, const float* __restrict__ b2p,
    float* __restrict__ Cout, int qkv)
{
    extern __shared__ __half sm[];

    const int tid  = threadIdx.x;
    const int lane = tid & 31;
    const int w    = tid >> 5;          // 0..3
    const int lq = lane >> 2, lr = lane & 3;
    const int wm = (w >> 1) * 64;       // 0 or 64
    const int wn = (w & 1) * 32;        // 0 or 32
    const int brow = blockIdx.y * 128;
    const int K = HIDDEN;

    const __half* B; const float* bias; int N, bcol, mode;
    int bx = blockIdx.x;
    if (qkv) {
        if (bx < 32)      { B = W0; bias = b0p; N = HIDDEN; bcol = bx * 64;        mode = 1; }
        else if (bx < 40) { B = W1; bias = b1p; N = KVSIZE; bcol = (bx - 32) * 64; mode = 2; }
        else              { B = W2; bias = b2p; N = KVSIZE; bcol = (bx - 40) * 64; mode = 3; }
    } else                { B = W0; bias = b0p; N = HIDDEN; bcol = bx * 64;        mode = 0; }

    auto issue = [&](int st, int kt) {
        __half* As = sm + st * HSTG;
        __half* Bs = As + 128 * PA;
#pragma unroll
        for (int i = 0; i < 4; i++) {          // A: 128 rows x 32 halves = 512 x 16B
            int ch = tid + i * 128;
            int r = ch >> 2, c8 = (ch & 3) << 3;
            unsigned d = sptr(As + r * PA + c8);
            const __half* s = A + (size_t)(brow + r) * K + kt + c8;
            asm volatile("cp.async.ca.shared.global [%0], [%1], 16;" :: "r"(d), "l"(s));
        }
#pragma unroll
        for (int i = 0; i < 2; i++) {          // B: 32 rows x 64 halves = 256 x 16B
            int ch = tid + i * 128;
            int r = ch >> 3, c8 = (ch & 7) << 3;
            unsigned d = sptr(Bs + r * PB + c8);
            const __half* s = B + (size_t)(kt + r) * N + bcol + c8;
            asm volatile("cp.async.ca.shared.global [%0], [%1], 16;" :: "r"(d), "l"(s));
        }
        asm volatile("cp.async.commit_group;");
    };

    issue(0, 0);
    issue(1, 32);

    float c[4][4][4] = {};
    const int T = K / 32;
    for (int t = 0; t < T; t++) {
        asm volatile("cp.async.wait_group 1;");   // stage t landed
        __syncthreads();                          // compute(t-1) fully done
        if (t + 2 < T) issue((t + 2) % 3, (t + 2) * 32);

        const __half* Asf = sm + (t % 3) * HSTG;
        const __half* Bsf = Asf + 128 * PA;
#pragma unroll
        for (int kk = 0; kk < 32; kk += 16) {
            unsigned a[4][4], bf[4][2];
#pragma unroll
            for (int mi = 0; mi < 4; mi++) {
                unsigned ad = sptr(Asf + (size_t)(wm + mi * 16 + (lane & 15)) * PA
                                   + kk + ((lane >> 4) << 3));
                ldsm4(a[mi][0], a[mi][1], a[mi][2], a[mi][3], ad);
            }
#pragma unroll
            for (int np = 0; np < 2; np++) {
                int m = lane >> 3;
                int krow = kk + (m & 1) * 8 + (lane & 7);
                int ncol = wn + np * 16 + (m >> 1) * 8;
                unsigned bd = sptr(Bsf + (size_t)krow * PB + ncol);
                ldsm4t(bf[np * 2][0], bf[np * 2][1], bf[np * 2 + 1][0], bf[np * 2 + 1][1], bd);
            }
#pragma unroll
            for (int mi = 0; mi < 4; mi++)
#pragma unroll
                for (int ni = 0; ni < 4; ni++)
                    mma_f16(c[mi][ni], a[mi][0], a[mi][1], a[mi][2], a[mi][3],
                            bf[ni][0], bf[ni][1]);
        }
    }

    // Epilogue (fp32 accum + bias)
#pragma unroll
    for (int mi = 0; mi < 4; mi++)
#pragma unroll
        for (int ni = 0; ni < 4; ni++) {
            int row = brow + wm + mi * 16 + lq;
            int col = bcol + wn + ni * 8 + 2 * lr;
            float v0 = c[mi][ni][0] + bias[col];
            float v1 = c[mi][ni][1] + bias[col + 1];
            float v2 = c[mi][ni][2] + bias[col];
            float v3 = c[mi][ni][3] + bias[col + 1];
            if (mode == 0) {
                *(float2*)&Cout[(size_t)row * N + col]       = make_float2(v0, v1);
                *(float2*)&Cout[(size_t)(row + 8) * N + col] = make_float2(v2, v3);
            } else if (mode == 1) {            // Q: prescale 1/8, fp16
                *(__half2*)&g_Qh[(size_t)row * HIDDEN + col] =
                    __floats2half2_rn(v0 * 0.125f, v1 * 0.125f);
                *(__half2*)&g_Qh[(size_t)(row + 8) * HIDDEN + col] =
                    __floats2half2_rn(v2 * 0.125f, v3 * 0.125f);
            } else if (mode == 2) {            // K: fp16
                *(__half2*)&g_Kh[(size_t)row * KVSIZE + col] = __floats2half2_rn(v0, v1);
                *(__half2*)&g_Kh[(size_t)(row + 8) * KVSIZE + col] = __floats2half2_rn(v2, v3);
            } else {                           // V: fp16, transposed scatter
                size_t base0 = ((size_t)((row >> 11) * 512) + col) * SEQ + (row & 2047);
                g_Vh[base0]       = __float2half(v0);
                g_Vh[base0 + SEQ] = __float2half(v1);
                int r8 = row + 8;
                size_t base1 = ((size_t)((r8 >> 11) * 512) + col) * SEQ + (r8 & 2047);
                g_Vh[base1]       = __float2half(v2);
                g_Vh[base1 + SEQ] = __float2half(v3);
            }
        }
}

// ---------------------------------------------------------------------------
// Flash attention (unchanged, known-good): fp16 mma.sync, cp.async K/V,
// one barrier per tile, P via C-frag->A-frag repack.
// ---------------------------------------------------------------------------
__global__ __launch_bounds__(128) void flash_cp(const float* __restrict__ mask)
{
    __shared__ unsigned Qw[64][36];
    __shared__ unsigned Kw[2][64][36];
    __shared__ unsigned Vw[2][64][36];

    const int tid  = threadIdx.x;
    const int lane = tid & 31;
    const int w    = tid >> 5;
    const int lq = lane >> 2, lr = lane & 3;
    const int h   = blockIdx.y;
    const int b   = blockIdx.z;
    const int kvh = h >> 2;
    const int m0  = b * SEQ + blockIdx.x * 64;
    const int q0  = w * 16;
    const float* maskb = mask + b * SEQ;
    const __half* Vg = g_Vh + (size_t)(b * 8 + kvh) * 64 * SEQ;

    auto issue_kv = [&](int buf, int kt) {
#pragma unroll
        for (int i = 0; i < 4; i++) {
            int ch = i * 128 + tid;
            int r = ch >> 3, c8 = (ch & 7) << 3;
            unsigned dk = sptr(&Kw[buf][r][c8 >> 1]);
            const __half* sk = g_Kh + (size_t)(b * SEQ + kt + r) * KVSIZE + kvh * 64 + c8;
            asm volatile("cp.async.ca.shared.global [%0], [%1], 16;" :: "r"(dk), "l"(sk));
            unsigned dv = sptr(&Vw[buf][r][c8 >> 1]);
            const __half* sv = Vg + (size_t)r * SEQ + kt + c8;
            asm volatile("cp.async.ca.shared.global [%0], [%1], 16;" :: "r"(dv), "l"(sv));
        }
        asm volatile("cp.async.commit_group;");
    };

#pragma unroll
    for (int i = 0; i < 4; i++) {
        int ch = i * 128 + tid;
        int r = ch >> 3, c8 = (ch & 7) << 3;
        unsigned d = sptr(&Qw[r][c8 >> 1]);
        const __half* s = g_Qh + (size_t)(m0 + r) * HIDDEN + h * HEAD_DIM + c8;
        asm volatile("cp.async.ca.shared.global [%0], [%1], 16;" :: "r"(d), "l"(s));
    }
    issue_kv(0, 0);
    asm volatile("cp.async.wait_group 0;");
    __syncthreads();

    unsigned qf[4][4];
#pragma unroll
    for (int kc = 0; kc < 4; kc++) {
        qf[kc][0] = Qw[q0 + lq][kc * 8 + lr];
        qf[kc][1] = Qw[q0 + 8 + lq][kc * 8 + lr];
        qf[kc][2] = Qw[q0 + lq][kc * 8 + 4 + lr];
        qf[kc][3] = Qw[q0 + 8 + lq][kc * 8 + 4 + lr];
    }

    float m1 = -1e30f, m2 = -1e30f, l1 = 0.f, l2 = 0.f;
    float o[8][4] = {};

    for (int t = 0; t < SEQ / 64; t++) {
        if (t) {
            asm volatile("cp.async.wait_group 0;");
            __syncthreads();
        }
        if (t + 1 < SEQ / 64) issue_kv((t + 1) & 1, (t + 1) * 64);

        const unsigned (*Kb)[36] = Kw[t & 1];
        const unsigned (*Vb)[36] = Vw[t & 1];
        const int kt = t * 64;

        float s[8][4] = {};
#pragma unroll
        for (int kc = 0; kc < 4; kc++)
#pragma unroll
            for (int ni = 0; ni < 8; ni++) {
                unsigned b0 = Kb[ni * 8 + lq][kc * 8 + lr];
                unsigned b1 = Kb[ni * 8 + lq][kc * 8 + 4 + lr];
                mma_f16(s[ni], qf[kc][0], qf[kc][1], qf[kc][2], qf[kc][3], b0, b1);
            }

#pragma unroll
        for (int ni = 0; ni < 8; ni++) {
            float2 mv = *(const float2*)&maskb[kt + ni * 8 + 2 * lr];
            s[ni][0] += mv.x; s[ni][1] += mv.y;
            s[ni][2] += mv.x; s[ni][3] += mv.y;
        }

        float tm1 = -1e30f, tm2 = -1e30f;
#pragma unroll
        for (int ni = 0; ni < 8; ni++) {
            tm1 = fmaxf(tm1, fmaxf(s[ni][0], s[ni][1]));
            tm2 = fmaxf(tm2, fmaxf(s[ni][2], s[ni][3]));
        }
        tm1 = fmaxf(tm1, __shfl_xor_sync(0xffffffffu, tm1, 1));
        tm1 = fmaxf(tm1, __shfl_xor_sync(0xffffffffu, tm1, 2));
        tm2 = fmaxf(tm2, __shfl_xor_sync(0xffffffffu, tm2, 1));
        tm2 = fmaxf(tm2, __shfl_xor_sync(0xffffffffu, tm2, 2));
        float nm1 = fmaxf(m1, tm1), nm2 = fmaxf(m2, tm2);
        float corr1 = __expf(m1 - nm1), corr2 = __expf(m2 - nm2);
        m1 = nm1; m2 = nm2;
        float ts1 = 0.f, ts2 = 0.f;
#pragma unroll
        for (int ni = 0; ni < 8; ni++) {
            s[ni][0] = __expf(s[ni][0] - nm1); ts1 += s[ni][0];
            s[ni][1] = __expf(s[ni][1] - nm1); ts1 += s[ni][1];
            s[ni][2] = __expf(s[ni][2] - nm2); ts2 += s[ni][2];
            s[ni][3] = __expf(s[ni][3] - nm2); ts2 += s[ni][3];
        }
        ts1 += __shfl_xor_sync(0xffffffffu, ts1, 1);
        ts1 += __shfl_xor_sync(0xffffffffu, ts1, 2);
        ts2 += __shfl_xor_sync(0xffffffffu, ts2, 1);
        ts2 += __shfl_xor_sync(0xffffffffu, ts2, 2);
        l1 = l1 * corr1 + ts1;
        l2 = l2 * corr2 + ts2;
#pragma unroll
        for (int di = 0; di < 8; di++) {
            o[di][0] *= corr1; o[di][1] *= corr1;
            o[di][2] *= corr2; o[di][3] *= corr2;
        }

#pragma unroll
        for (int kc = 0; kc < 4; kc++) {
            unsigned pa0 = h2pack(s[2 * kc][0],     s[2 * kc][1]);
            unsigned pa1 = h2pack(s[2 * kc][2],     s[2 * kc][3]);
            unsigned pa2 = h2pack(s[2 * kc + 1][0], s[2 * kc + 1][1]);
            unsigned pa3 = h2pack(s[2 * kc + 1][2], s[2 * kc + 1][3]);
#pragma unroll
            for (int di = 0; di < 8; di++) {
                unsigned b0 = Vb[di * 8 + lq][kc * 8 + lr];
                unsigned b1 = Vb[di * 8 + lq][kc * 8 + 4 + lr];
                mma_f16(o[di], pa0, pa1, pa2, pa3, b0, b1);
            }
        }
    }

    float inv1 = 1.0f / l1, inv2 = 1.0f / l2;
#pragma unroll
    for (int di = 0; di < 8; di++) {
        int col  = h * HEAD_DIM + di * 8 + 2 * lr;
        int row1 = m0 + q0 + lq;
        *(__half2*)&g_Ah[(size_t)row1 * HIDDEN + col] =
            __floats2half2_rn(o[di][0] * inv1, o[di][1] * inv1);
        *(__half2*)&g_Ah[(size_t)(row1 + 8) * HIDDEN + col] =
            __floats2half2_rn(o[di][2] * inv2, o[di][3] * inv2);
    }
}

// ---------------------------------------------------------------------------
extern "C" void kernel_launch(void* const* d_in, const int* in_sizes, int n_in,
                              void* d_out, int out_size)
{
    const float* x    = (const float*)d_in[0];
    const float* mask = (const float*)d_in[1];
    const float* Wq   = (const float*)d_in[2];
    const float* bq   = (const float*)d_in[3];
    const float* Wk   = (const float*)d_in[4];
    const float* bk   = (const float*)d_in[5];
    const float* Wv   = (const float*)d_in[6];
    const float* bv   = (const float*)d_in[7];
    const float* Wo   = (const float*)d_in[8];
    const float* bo   = (const float*)d_in[9];
    float* out = (float*)d_out;

    __half *xh, *wqh, *wkh, *wvh, *woh, *ah;
    cudaGetSymbolAddress((void**)&xh,  g_xh);
    cudaGetSymbolAddress((void**)&wqh, g_Wqh);
    cudaGetSymbolAddress((void**)&wkh, g_Wkh);
    cudaGetSymbolAddress((void**)&wvh, g_Wvh);
    cudaGetSymbolAddress((void**)&woh, g_Woh);
    cudaGetSymbolAddress((void**)&ah,  g_Ah);

    const int GSMEM = 3 * HSTG * (int)sizeof(__half);   // 44544 B
    cudaFuncSetAttribute((const void*)gemm_h,
                         cudaFuncAttributeMaxDynamicSharedMemorySize, GSMEM);

    // fp32 -> fp16 conversions
    f2h<<<MTOT * HIDDEN / 4 / 256, 256>>>(x,  xh,  MTOT * HIDDEN);
    f2h<<<HIDDEN * HIDDEN / 4 / 256, 256>>>(Wq, wqh, HIDDEN * HIDDEN);
    f2h<<<HIDDEN * KVSIZE / 4 / 256, 256>>>(Wk, wkh, HIDDEN * KVSIZE);
    f2h<<<HIDDEN * KVSIZE / 4 / 256, 256>>>(Wv, wvh, HIDDEN * KVSIZE);
    f2h<<<HIDDEN * HIDDEN / 4 / 256, 256>>>(Wo, woh, HIDDEN * HIDDEN);

    // Fused QKV projections (grid.x: 32 Q + 8 K + 8 V col-tiles of 64)
    gemm_h<<<dim3(48, MTOT / 128), 128, GSMEM>>>(xh, wqh, bq, wkh, bk, wvh, bv, nullptr, 1);
    // Flash attention
    flash_cp<<<dim3(SEQ / 64, 32, BATCH), dim3(128)>>>(mask);
    // out = A @ Wo + bo
    gemm_h<<<dim3(32, MTOT / 128), 128, GSMEM>>>(ah, woh, bo, nullptr, nullptr,
                                                 nullptr, nullptr, out, 0);
}

// round 16
// speedup vs baseline: 7.3596x; 1.0509x over previous
#include <cuda_runtime.h>
#include <cuda_fp16.h>
#include <cstdint>

#define HIDDEN   2048
#define KVSIZE   512
#define HEAD_DIM 64
#define BATCH    2
#define SEQ      2048
#define MTOT     (BATCH * SEQ)

// Scratch (device globals: allocation inside kernel_launch is forbidden)
__device__ __half g_xh [MTOT * HIDDEN];    // x fp16, [m][k]
__device__ __half g_Wqh[HIDDEN * HIDDEN];  // weights fp16, [k][n]
__device__ __half g_Wkh[HIDDEN * KVSIZE];
__device__ __half g_Wvh[HIDDEN * KVSIZE];
__device__ __half g_Woh[HIDDEN * HIDDEN];
__device__ __half g_Qh [MTOT * HIDDEN];    // PRESCALED by 0.125, [m][h*64+d]
__device__ __half g_Kh [MTOT * KVSIZE];    // [m][kvh*64+d]
__device__ __half g_Vh [MTOT * KVSIZE];    // TRANSPOSED [(b*8+kvh)*64+d][seq]
__device__ __half g_Ah [MTOT * HIDDEN];    // attention out fp16, [m][h*64+d]

// ---------------------------------------------------------------------------
// helpers
// ---------------------------------------------------------------------------
__device__ __forceinline__ unsigned h2pack(float lo, float hi) {
    unsigned r;
    asm("cvt.rn.f16x2.f32 %0, %1, %2;" : "=r"(r) : "f"(hi), "f"(lo));
    return r;
}
__device__ __forceinline__ unsigned sptr(const void* p) {
    return (unsigned)__cvta_generic_to_shared(p);
}
__device__ __forceinline__ void mma_f16(float c[4],
                                        unsigned a0, unsigned a1, unsigned a2, unsigned a3,
                                        unsigned b0, unsigned b1) {
    asm("mma.sync.aligned.m16n8k16.row.col.f32.f16.f16.f32 "
        "{%0,%1,%2,%3}, {%4,%5,%6,%7}, {%8,%9}, {%0,%1,%2,%3};"
        : "+f"(c[0]), "+f"(c[1]), "+f"(c[2]), "+f"(c[3])
        : "r"(a0), "r"(a1), "r"(a2), "r"(a3), "r"(b0), "r"(b1));
}
__device__ __forceinline__ void ldsm4(unsigned& r0, unsigned& r1, unsigned& r2, unsigned& r3,
                                      unsigned addr) {
    asm volatile("ldmatrix.sync.aligned.m8n8.x4.shared.b16 {%0,%1,%2,%3}, [%4];"
                 : "=r"(r0), "=r"(r1), "=r"(r2), "=r"(r3) : "r"(addr));
}
__device__ __forceinline__ void ldsm4t(unsigned& r0, unsigned& r1, unsigned& r2, unsigned& r3,
                                       unsigned addr) {
    asm volatile("ldmatrix.sync.aligned.m8n8.x4.trans.shared.b16 {%0,%1,%2,%3}, [%4];"
                 : "=r"(r0), "=r"(r1), "=r"(r2), "=r"(r3) : "r"(addr));
}

// ---------------------------------------------------------------------------
// fp32 -> fp16 bulk convert
// ---------------------------------------------------------------------------
__global__ __launch_bounds__(256) void f2h(const float* __restrict__ s,
                                           __half* __restrict__ d, int n) {
    int i = (blockIdx.x * 256 + threadIdx.x) * 4;
    if (i < n) {
        float4 v = *(const float4*)(s + i);
        *(__half2*)(d + i)     = __floats2half2_rn(v.x, v.y);
        *(__half2*)(d + i + 2) = __floats2half2_rn(v.z, v.w);
    }
}

// ---------------------------------------------------------------------------
// fp16 GEMM: C = A@B + bias. 128x64 block tile, K-chunk 64, 128 thr (4 warps),
// warp tile 64x32. 2-stage cp.async pipeline with ONE sync per chunk:
//   wait(stage t) -> sync(compute t-1 done) -> issue(t+1 into vacated buf)
//   -> compute(t).  T = 32 barrier intervals (was 64), 4 blocks/SM.
// A pitch 72 halves (rows stride 36 words ≡4 mod 32 -> ldmatrix phase banks
// {0,4,...,28}, conflict-free); B pitch 72 likewise.
// qkv != 0: fused QKV, grid.x = 48: [0,32) Q, [32,40) K, [40,48) V.
// qkv == 0: O projection, fp32 out.
// ---------------------------------------------------------------------------
#define PA 72
#define PB 72
#define KC 64
#define HSTG (128 * PA + KC * PB)   // 13824 halves / stage (27648 B)

__global__ __launch_bounds__(128) void gemm_h(
    const __half* __restrict__ A,
    const __half* __restrict__ W0, const float* __restrict__ b0p,
    const __half* __restrict__ W1, const float* __restrict__ b1p,
    const __half* __restrict__ W2, const float* __restrict__ b2p,
    float* __restrict__ Cout, int qkv)
{
    extern __shared__ __half sm[];

    const int tid  = threadIdx.x;
    const int lane = tid & 31;
    const int w    = tid >> 5;          // 0..3
    const int lq = lane >> 2, lr = lane & 3;
    const int wm = (w >> 1) * 64;       // 0 or 64
    const int wn = (w & 1) * 32;        // 0 or 32
    const int brow = blockIdx.y * 128;
    const int K = HIDDEN;

    const __half* B; const float* bias; int N, bcol, mode;
    int bx = blockIdx.x;
    if (qkv) {
        if (bx < 32)      { B = W0; bias = b0p; N = HIDDEN; bcol = bx * 64;        mode = 1; }
        else if (bx < 40) { B = W1; bias = b1p; N = KVSIZE; bcol = (bx - 32) * 64; mode = 2; }
        else              { B = W2; bias = b2p; N = KVSIZE; bcol = (bx - 40) * 64; mode = 3; }
    } else                { B = W0; bias = b0p; N = HIDDEN; bcol = bx * 64;        mode = 0; }

    auto issue = [&](int st, int kt) {
        __half* As = sm + st * HSTG;
        __half* Bs = As + 128 * PA;
#pragma unroll
        for (int i = 0; i < 8; i++) {          // A: 128 rows x 64 halves = 1024 x 16B
            int ch = tid + i * 128;
            int r = ch >> 3, c8 = (ch & 7) << 3;
            unsigned d = sptr(As + r * PA + c8);
            const __half* s = A + (size_t)(brow + r) * K + kt + c8;
            asm volatile("cp.async.ca.shared.global [%0], [%1], 16;" :: "r"(d), "l"(s));
        }
#pragma unroll
        for (int i = 0; i < 4; i++) {          // B: 64 rows x 64 halves = 512 x 16B
            int ch = tid + i * 128;
            int r = ch >> 3, c8 = (ch & 7) << 3;
            unsigned d = sptr(Bs + r * PB + c8);
            const __half* s = B + (size_t)(kt + r) * N + bcol + c8;
            asm volatile("cp.async.ca.shared.global [%0], [%1], 16;" :: "r"(d), "l"(s));
        }
        asm volatile("cp.async.commit_group;");
    };

    issue(0, 0);

    float c[4][4][4] = {};
    const int T = K / KC;                      // 32
    for (int t = 0; t < T; t++) {
        asm volatile("cp.async.wait_group 0;");   // stage t landed
        __syncthreads();                          // compute(t-1) done everywhere
        if (t + 1 < T) issue((t + 1) & 1, (t + 1) * KC);  // into vacated buffer

        const __half* Asf = sm + (t & 1) * HSTG;
        const __half* Bsf = Asf + 128 * PA;
#pragma unroll
        for (int kk = 0; kk < KC; kk += 16) {
            unsigned a[4][4], bf[4][2];
#pragma unroll
            for (int mi = 0; mi < 4; mi++) {
                unsigned ad = sptr(Asf + (size_t)(wm + mi * 16 + (lane & 15)) * PA
                                   + kk + ((lane >> 4) << 3));
                ldsm4(a[mi][0], a[mi][1], a[mi][2], a[mi][3], ad);
            }
#pragma unroll
            for (int np = 0; np < 2; np++) {
                int m = lane >> 3;
                int krow = kk + (m & 1) * 8 + (lane & 7);
                int ncol = wn + np * 16 + (m >> 1) * 8;
                unsigned bd = sptr(Bsf + (size_t)krow * PB + ncol);
                ldsm4t(bf[np * 2][0], bf[np * 2][1], bf[np * 2 + 1][0], bf[np * 2 + 1][1], bd);
            }
#pragma unroll
            for (int mi = 0; mi < 4; mi++)
#pragma unroll
                for (int ni = 0; ni < 4; ni++)
                    mma_f16(c[mi][ni], a[mi][0], a[mi][1], a[mi][2], a[mi][3],
                            bf[ni][0], bf[ni][1]);
        }
    }

    // Epilogue (fp32 accum + bias)
#pragma unroll
    for (int mi = 0; mi < 4; mi++)
#pragma unroll
        for (int ni = 0; ni < 4; ni++) {
            int row = brow + wm + mi * 16 + lq;
            int col = bcol + wn + ni * 8 + 2 * lr;
            float v0 = c[mi][ni][0] + bias[col];
            float v1 = c[mi][ni][1] + bias[col + 1];
            float v2 = c[mi][ni][2] + bias[col];
            float v3 = c[mi][ni][3] + bias[col + 1];
            if (mode == 0) {
                *(float2*)&Cout[(size_t)row * N + col]       = make_float2(v0, v1);
                *(float2*)&Cout[(size_t)(row + 8) * N + col] = make_float2(v2, v3);
            } else if (mode == 1) {            // Q: prescale 1/8, fp16
                *(__half2*)&g_Qh[(size_t)row * HIDDEN + col] =
                    __floats2half2_rn(v0 * 0.125f, v1 * 0.125f);
                *(__half2*)&g_Qh[(size_t)(row + 8) * HIDDEN + col] =
                    __floats2half2_rn(v2 * 0.125f, v3 * 0.125f);
            } else if (mode == 2) {            // K: fp16
                *(__half2*)&g_Kh[(size_t)row * KVSIZE + col] = __floats2half2_rn(v0, v1);
                *(__half2*)&g_Kh[(size_t)(row + 8) * KVSIZE + col] = __floats2half2_rn(v2, v3);
            } else {                           // V: fp16, transposed scatter
                size_t base0 = ((size_t)((row >> 11) * 512) + col) * SEQ + (row & 2047);
                g_Vh[base0]       = __float2half(v0);
                g_Vh[base0 + SEQ] = __float2half(v1);
                int r8 = row + 8;
                size_t base1 = ((size_t)((r8 >> 11) * 512) + col) * SEQ + (r8 & 2047);
                g_Vh[base1]       = __float2half(v2);
                g_Vh[base1 + SEQ] = __float2half(v3);
            }
        }
}

// ---------------------------------------------------------------------------
// Flash attention (unchanged, known-good): fp16 mma.sync, cp.async K/V,
// one barrier per tile, P via C-frag->A-frag repack.
// ---------------------------------------------------------------------------
__global__ __launch_bounds__(128) void flash_cp(const float* __restrict__ mask)
{
    __shared__ unsigned Qw[64][36];
    __shared__ unsigned Kw[2][64][36];
    __shared__ unsigned Vw[2][64][36];

    const int tid  = threadIdx.x;
    const int lane = tid & 31;
    const int w    = tid >> 5;
    const int lq = lane >> 2, lr = lane & 3;
    const int h   = blockIdx.y;
    const int b   = blockIdx.z;
    const int kvh = h >> 2;
    const int m0  = b * SEQ + blockIdx.x * 64;
    const int q0  = w * 16;
    const float* maskb = mask + b * SEQ;
    const __half* Vg = g_Vh + (size_t)(b * 8 + kvh) * 64 * SEQ;

    auto issue_kv = [&](int buf, int kt) {
#pragma unroll
        for (int i = 0; i < 4; i++) {
            int ch = i * 128 + tid;
            int r = ch >> 3, c8 = (ch & 7) << 3;
            unsigned dk = sptr(&Kw[buf][r][c8 >> 1]);
            const __half* sk = g_Kh + (size_t)(b * SEQ + kt + r) * KVSIZE + kvh * 64 + c8;
            asm volatile("cp.async.ca.shared.global [%0], [%1], 16;" :: "r"(dk), "l"(sk));
            unsigned dv = sptr(&Vw[buf][r][c8 >> 1]);
            const __half* sv = Vg + (size_t)r * SEQ + kt + c8;
            asm volatile("cp.async.ca.shared.global [%0], [%1], 16;" :: "r"(dv), "l"(sv));
        }
        asm volatile("cp.async.commit_group;");
    };

#pragma unroll
    for (int i = 0; i < 4; i++) {
        int ch = i * 128 + tid;
        int r = ch >> 3, c8 = (ch & 7) << 3;
        unsigned d = sptr(&Qw[r][c8 >> 1]);
        const __half* s = g_Qh + (size_t)(m0 + r) * HIDDEN + h * HEAD_DIM + c8;
        asm volatile("cp.async.ca.shared.global [%0], [%1], 16;" :: "r"(d), "l"(s));
    }
    issue_kv(0, 0);
    asm volatile("cp.async.wait_group 0;");
    __syncthreads();

    unsigned qf[4][4];
#pragma unroll
    for (int kc = 0; kc < 4; kc++) {
        qf[kc][0] = Qw[q0 + lq][kc * 8 + lr];
        qf[kc][1] = Qw[q0 + 8 + lq][kc * 8 + lr];
        qf[kc][2] = Qw[q0 + lq][kc * 8 + 4 + lr];
        qf[kc][3] = Qw[q0 + 8 + lq][kc * 8 + 4 + lr];
    }

    float m1 = -1e30f, m2 = -1e30f, l1 = 0.f, l2 = 0.f;
    float o[8][4] = {};

    for (int t = 0; t < SEQ / 64; t++) {
        if (t) {
            asm volatile("cp.async.wait_group 0;");
            __syncthreads();
        }
        if (t + 1 < SEQ / 64) issue_kv((t + 1) & 1, (t + 1) * 64);

        const unsigned (*Kb)[36] = Kw[t & 1];
        const unsigned (*Vb)[36] = Vw[t & 1];
        const int kt = t * 64;

        float s[8][4] = {};
#pragma unroll
        for (int kc = 0; kc < 4; kc++)
#pragma unroll
            for (int ni = 0; ni < 8; ni++) {
                unsigned b0 = Kb[ni * 8 + lq][kc * 8 + lr];
                unsigned b1 = Kb[ni * 8 + lq][kc * 8 + 4 + lr];
                mma_f16(s[ni], qf[kc][0], qf[kc][1], qf[kc][2], qf[kc][3], b0, b1);
            }

#pragma unroll
        for (int ni = 0; ni < 8; ni++) {
            float2 mv = *(const float2*)&maskb[kt + ni * 8 + 2 * lr];
            s[ni][0] += mv.x; s[ni][1] += mv.y;
            s[ni][2] += mv.x; s[ni][3] += mv.y;
        }

        float tm1 = -1e30f, tm2 = -1e30f;
#pragma unroll
        for (int ni = 0; ni < 8; ni++) {
            tm1 = fmaxf(tm1, fmaxf(s[ni][0], s[ni][1]));
            tm2 = fmaxf(tm2, fmaxf(s[ni][2], s[ni][3]));
        }
        tm1 = fmaxf(tm1, __shfl_xor_sync(0xffffffffu, tm1, 1));
        tm1 = fmaxf(tm1, __shfl_xor_sync(0xffffffffu, tm1, 2));
        tm2 = fmaxf(tm2, __shfl_xor_sync(0xffffffffu, tm2, 1));
        tm2 = fmaxf(tm2, __shfl_xor_sync(0xffffffffu, tm2, 2));
        float nm1 = fmaxf(m1, tm1), nm2 = fmaxf(m2, tm2);
        float corr1 = __expf(m1 - nm1), corr2 = __expf(m2 - nm2);
        m1 = nm1; m2 = nm2;
        float ts1 = 0.f, ts2 = 0.f;
#pragma unroll
        for (int ni = 0; ni < 8; ni++) {
            s[ni][0] = __expf(s[ni][0] - nm1); ts1 += s[ni][0];
            s[ni][1] = __expf(s[ni][1] - nm1); ts1 += s[ni][1];
            s[ni][2] = __expf(s[ni][2] - nm2); ts2 += s[ni][2];
            s[ni][3] = __expf(s[ni][3] - nm2); ts2 += s[ni][3];
        }
        ts1 += __shfl_xor_sync(0xffffffffu, ts1, 1);
        ts1 += __shfl_xor_sync(0xffffffffu, ts1, 2);
        ts2 += __shfl_xor_sync(0xffffffffu, ts2, 1);
        ts2 += __shfl_xor_sync(0xffffffffu, ts2, 2);
        l1 = l1 * corr1 + ts1;
        l2 = l2 * corr2 + ts2;
#pragma unroll
        for (int di = 0; di < 8; di++) {
            o[di][0] *= corr1; o[di][1] *= corr1;
            o[di][2] *= corr2; o[di][3] *= corr2;
        }

#pragma unroll
        for (int kc = 0; kc < 4; kc++) {
            unsigned pa0 = h2pack(s[2 * kc][0],     s[2 * kc][1]);
            unsigned pa1 = h2pack(s[2 * kc][2],     s[2 * kc][3]);
            unsigned pa2 = h2pack(s[2 * kc + 1][0], s[2 * kc + 1][1]);
            unsigned pa3 = h2pack(s[2 * kc + 1][2], s[2 * kc + 1][3]);
#pragma unroll
            for (int di = 0; di < 8; di++) {
                unsigned b0 = Vb[di * 8 + lq][kc * 8 + lr];
                unsigned b1 = Vb[di * 8 + lq][kc * 8 + 4 + lr];
                mma_f16(o[di], pa0, pa1, pa2, pa3, b0, b1);
            }
        }
    }

    float inv1 = 1.0f / l1, inv2 = 1.0f / l2;
#pragma unroll
    for (int di = 0; di < 8; di++) {
        int col  = h * HEAD_DIM + di * 8 + 2 * lr;
        int row1 = m0 + q0 + lq;
        *(__half2*)&g_Ah[(size_t)row1 * HIDDEN + col] =
            __floats2half2_rn(o[di][0] * inv1, o[di][1] * inv1);
        *(__half2*)&g_Ah[(size_t)(row1 + 8) * HIDDEN + col] =
            __floats2half2_rn(o[di][2] * inv2, o[di][3] * inv2);
    }
}

// ---------------------------------------------------------------------------
extern "C" void kernel_launch(void* const* d_in, const int* in_sizes, int n_in,
                              void* d_out, int out_size)
{
    const float* x    = (const float*)d_in[0];
    const float* mask = (const float*)d_in[1];
    const float* Wq   = (const float*)d_in[2];
    const float* bq   = (const float*)d_in[3];
    const float* Wk   = (const float*)d_in[4];
    const float* bk   = (const float*)d_in[5];
    const float* Wv   = (const float*)d_in[6];
    const float* bv   = (const float*)d_in[7];
    const float* Wo   = (const float*)d_in[8];
    const float* bo   = (const float*)d_in[9];
    float* out = (float*)d_out;

    __half *xh, *wqh, *wkh, *wvh, *woh, *ah;
    cudaGetSymbolAddress((void**)&xh,  g_xh);
    cudaGetSymbolAddress((void**)&wqh, g_Wqh);
    cudaGetSymbolAddress((void**)&wkh, g_Wkh);
    cudaGetSymbolAddress((void**)&wvh, g_Wvh);
    cudaGetSymbolAddress((void**)&woh, g_Woh);
    cudaGetSymbolAddress((void**)&ah,  g_Ah);

    const int GSMEM = 2 * HSTG * (int)sizeof(__half);   // 55296 B
    cudaFuncSetAttribute((const void*)gemm_h,
                         cudaFuncAttributeMaxDynamicSharedMemorySize, GSMEM);

    // fp32 -> fp16 conversions
    f2h<<<MTOT * HIDDEN / 4 / 256, 256>>>(x,  xh,  MTOT * HIDDEN);
    f2h<<<HIDDEN * HIDDEN / 4 / 256, 256>>>(Wq, wqh, HIDDEN * HIDDEN);
    f2h<<<HIDDEN * KVSIZE / 4 / 256, 256>>>(Wk, wkh, HIDDEN * KVSIZE);
    f2h<<<HIDDEN * KVSIZE / 4 / 256, 256>>>(Wv, wvh, HIDDEN * KVSIZE);
    f2h<<<HIDDEN * HIDDEN / 4 / 256, 256>>>(Wo, woh, HIDDEN * HIDDEN);

    // Fused QKV projections (grid.x: 32 Q + 8 K + 8 V col-tiles of 64)
    gemm_h<<<dim3(48, MTOT / 128), 128, GSMEM>>>(xh, wqh, bq, wkh, bk, wvh, bv, nullptr, 1);
    // Flash attention
    flash_cp<<<dim3(SEQ / 64, 32, BATCH), dim3(128)>>>(mask);
    // out = A @ Wo + bo
    gemm_h<<<dim3(32, MTOT / 128), 128, GSMEM>>>(ah, woh, bo, nullptr, nullptr,
                                                 nullptr, nullptr, out, 0);
}